// round 8
// baseline (speedup 1.0000x reference)
#include <cuda_runtime.h>
#include <cuda_fp16.h>

#define NN 100000
#define NE 1200000
#define NG 1000
#define H  64
#define TOT_E (NE + NN)
#define SLOT 64

// ---------------- scratch (no allocations allowed) ----------------
__device__ __half g_zh[NN * H];    // z in fp16 (values only; logits stay fp32)
__device__ float g_hout[NN * H];   // gat1 output / film2 input
__device__ float g_h2[NN * H];     // gat2 output / cls input
__device__ float g_zs[NN];
__device__ float g_zd[NN];
__device__ float g_w[NN * SLOT];   // per-edge softmax weights (normalized)
__device__ int   g_cnt[NN];
__device__ int   g_col2[NN * SLOT];
__device__ float g_gamma1[NG * H], g_beta1[NG * H];
__device__ float g_gamma2[NG * H], g_beta2[NG * H];

// ---------------- climber MLP + FiLM params, fused with g_cnt zeroing ----------------
__global__ void k_climber_zero(const float* __restrict__ climber,
                               const float* __restrict__ ln_g, const float* __restrict__ ln_b,
                               const float* __restrict__ W_c,  const float* __restrict__ b_c,
                               const float* __restrict__ Wf1,  const float* __restrict__ bf1,
                               const float* __restrict__ Wf2,  const float* __restrict__ bf2) {
    if (blockIdx.x >= NG) {
        int i = (blockIdx.x - NG) * 128 + threadIdx.x;
        if (i < NN) g_cnt[i] = 0;
        return;
    }
    __shared__ float cv[6], cn[6], c_sh[H];
    int g = blockIdx.x;
    int t = threadIdx.x;
    if (t < 6) cv[t] = climber[g * 6 + t];
    __syncthreads();
    float mu = (cv[0] + cv[1] + cv[2] + cv[3] + cv[4] + cv[5]) * (1.0f / 6.0f);
    float var = 0.f;
#pragma unroll
    for (int k = 0; k < 6; k++) { float d = cv[k] - mu; var += d * d; }
    var *= (1.0f / 6.0f);
    float rstd = rsqrtf(var + 1e-5f);
    if (t < 6) cn[t] = (cv[t] - mu) * rstd * ln_g[t] + ln_b[t];
    __syncthreads();
    if (t < H) {
        float a = b_c[t];
#pragma unroll
        for (int k = 0; k < 6; k++) a += cn[k] * W_c[k * H + t];
        c_sh[t] = fmaxf(a, 0.f);
    }
    __syncthreads();
    float a1 = bf1[t], a2 = bf2[t];
    for (int k = 0; k < H; k++) {
        float cc = c_sh[k];
        a1 += cc * Wf1[k * 128 + t];
        a2 += cc * Wf2[k * 128 + t];
    }
    if (t < H) { g_gamma1[g * H + t] = a1; g_gamma2[g * H + t] = a2; }
    else       { g_beta1[g * H + t - H] = a1; g_beta2[g * H + t - H] = a2; }
}

// ---------------- direct padded-adjacency fill (count == placement) ----------------
__global__ void k_fill(const int* __restrict__ ei) {
    int idx = blockIdx.x * blockDim.x + threadIdx.x;
    if (idx >= TOT_E) return;
    int s, d;
    if (idx < NE) { s = ei[idx]; d = ei[NE + idx]; }
    else          { s = d = idx - NE; }
    int pos = atomicAdd(&g_cnt[d], 1);
    if (pos < SLOT) g_col2[d * SLOT + pos] = s;
}

// ---------------- FiLM (+ fused input proj for layer 0) + z = hf@Wg, zs, zd ----------------
// 32 nodes per block, 4 nodes per warp, 2 outputs per lane
__global__ void k_film_z(int layer, const float* __restrict__ x,
                         const int* __restrict__ batch,
                         const float* __restrict__ Win, const float* __restrict__ bin,
                         const float* __restrict__ Wg,
                         const float* __restrict__ a_s,
                         const float* __restrict__ a_d) {
    __shared__ float sW[H][H];      // sW[k][j]
    __shared__ __align__(16) float sht[H][36];
    __shared__ float sWin[6][H];
    __shared__ float sbin[H];
    __shared__ float sx[32][8];
    __shared__ int   sb[32];
    int t = threadIdx.x;
    int n0 = blockIdx.x * 32;
    for (int i = t; i < H * H; i += 256) sW[i >> 6][i & 63] = Wg[i];
    if (t < 32) sb[t] = batch[n0 + t];
    if (layer == 0) {
        for (int i = t; i < 6 * H; i += 256) sWin[i >> 6][i & 63] = Win[i];
        if (t < H) sbin[t] = bin[t];
        sx[t >> 3][t & 7] = x[(n0 + (t >> 3)) * 8 + (t & 7)];
    }
    __syncthreads();
    const float* gam = (layer == 0) ? g_gamma1 : g_gamma2;
    const float* bet = (layer == 0) ? g_beta1 : g_beta2;
    for (int idx = t; idx < 32 * H; idx += 256) {
        int nl = idx >> 6, j = idx & 63;
        int n = n0 + nl;
        int b = sb[nl];
        float hv;
        if (layer == 0) {
            hv = sbin[j];
#pragma unroll
            for (int k = 0; k < 6; k++) hv += sx[nl][k] * sWin[k][j];
        } else {
            hv = g_hout[n * H + j];
        }
        sht[j][nl] = hv * (1.f + gam[b * H + j]) + bet[b * H + j];
    }
    __syncthreads();

    int w = t >> 5, lane = t & 31;
    float a00 = 0.f, a01 = 0.f, a10 = 0.f, a11 = 0.f;
    float a20 = 0.f, a21 = 0.f, a30 = 0.f, a31 = 0.f;
#pragma unroll
    for (int k = 0; k < H; k++) {
        float2 wv = *(const float2*)&sW[k][2 * lane];
        float4 hv = *(const float4*)&sht[k][w * 4];
        a00 += hv.x * wv.x; a01 += hv.x * wv.y;
        a10 += hv.y * wv.x; a11 += hv.y * wv.y;
        a20 += hv.z * wv.x; a21 += hv.z * wv.y;
        a30 += hv.w * wv.x; a31 += hv.w * wv.y;
    }
    int nb = n0 + w * 4;
    // z stored fp16 (values); logits below stay fp32
    *(__half2*)&g_zh[(nb + 0) * H + 2 * lane] = __floats2half2_rn(a00, a01);
    *(__half2*)&g_zh[(nb + 1) * H + 2 * lane] = __floats2half2_rn(a10, a11);
    *(__half2*)&g_zh[(nb + 2) * H + 2 * lane] = __floats2half2_rn(a20, a21);
    *(__half2*)&g_zh[(nb + 3) * H + 2 * lane] = __floats2half2_rn(a30, a31);
    float2 as = *(const float2*)&a_s[2 * lane];
    float2 ad = *(const float2*)&a_d[2 * lane];
    float r0 = a00 * as.x + a01 * as.y, q0 = a00 * ad.x + a01 * ad.y;
    float r1 = a10 * as.x + a11 * as.y, q1 = a10 * ad.x + a11 * ad.y;
    float r2 = a20 * as.x + a21 * as.y, q2 = a20 * ad.x + a21 * ad.y;
    float r3 = a30 * as.x + a31 * as.y, q3 = a30 * ad.x + a31 * ad.y;
#pragma unroll
    for (int o = 16; o; o >>= 1) {
        r0 += __shfl_xor_sync(0xffffffffu, r0, o);
        r1 += __shfl_xor_sync(0xffffffffu, r1, o);
        r2 += __shfl_xor_sync(0xffffffffu, r2, o);
        r3 += __shfl_xor_sync(0xffffffffu, r3, o);
        q0 += __shfl_xor_sync(0xffffffffu, q0, o);
        q1 += __shfl_xor_sync(0xffffffffu, q1, o);
        q2 += __shfl_xor_sync(0xffffffffu, q2, o);
        q3 += __shfl_xor_sync(0xffffffffu, q3, o);
    }
    if (lane == 0) {
        g_zs[nb + 0] = r0; g_zd[nb + 0] = q0;
        g_zs[nb + 1] = r1; g_zd[nb + 1] = q1;
        g_zs[nb + 2] = r2; g_zd[nb + 2] = q2;
        g_zs[nb + 3] = r3; g_zd[nb + 3] = q3;
    }
}

// ---------------- softmax weights: one THREAD per dst node ----------------
// Pass 1: online max+sum over neighbor logits (fp32, exact reference math),
// staging raw logits e into g_w. Pass 2: rewrite g_w with exp(e-m)/sum.
__global__ void k_softmax() {
    int n = blockIdx.x * blockDim.x + threadIdx.x;
    if (n >= NN) return;
    int cnt = min(g_cnt[n], SLOT);
    const int* __restrict__ cols = g_col2 + n * SLOT;
    float* __restrict__ wp = g_w + n * SLOT;
    float zdd = g_zd[n];
    float m = -1e30f, sum = 0.f;
    for (int i = 0; i < cnt; i++) {
        int s = cols[i];
        float tv = g_zs[s] + zdd;
        float e = fmaxf(tv, 0.2f * tv);   // leaky_relu(0.2)
        wp[i] = e;
        if (e > m) { sum = sum * __expf(m - e) + 1.f; m = e; }
        else       { sum += __expf(e - m); }
    }
    float invs = 1.f / (sum + 1e-16f);
    for (int i = 0; i < cnt; i++)
        wp[i] = __expf(wp[i] - m) * invs;
}

// ---------------- weighted gather: one warp per TWO dst nodes ----------------
// lane = nl*16 + g2*8 + ql : node-half nl, edge-subgroup g2, feature-lane ql.
// Each 8-lane group loads a full 128B fp16 z row per edge; groups g2=0/1 take
// even/odd edges. No shfl/sync in the loop; weights are preнормalized.
__global__ void k_gatherB(int layer, const float* __restrict__ bg) {
    int gw = (blockIdx.x * blockDim.x + threadIdx.x) >> 5;
    int lane = threadIdx.x & 31;
    int nl = lane >> 4, g2 = (lane >> 3) & 1, ql = lane & 7;
    int n = gw * 2 + nl;
    if (n >= NN) return;
    int cnt = min(g_cnt[n], SLOT);
    int cother = __shfl_xor_sync(0xffffffffu, cnt, 16);
    int cmax = max(cnt, cother);                 // warp-uniform
    int trips = (cmax + 1) >> 1;
    const int* __restrict__ cols = g_col2 + n * SLOT;
    const float* __restrict__ wp = g_w + n * SLOT;
    const __half* __restrict__ zbase = g_zh + 8 * ql;
    float acc[8] = {0.f, 0.f, 0.f, 0.f, 0.f, 0.f, 0.f, 0.f};
#pragma unroll 2
    for (int j = 0; j < trips; j++) {
        int i = 2 * j + g2;
        float wgt = 0.f;
        int of = 0;
        if (i < cnt) { wgt = wp[i]; of = cols[i] << 6; }
        float4 raw = *(const float4*)(zbase + of);
        const __half2* hp = (const __half2*)&raw;
        float2 f0 = __half22float2(hp[0]);
        float2 f1 = __half22float2(hp[1]);
        float2 f2 = __half22float2(hp[2]);
        float2 f3 = __half22float2(hp[3]);
        acc[0] += wgt * f0.x; acc[1] += wgt * f0.y;
        acc[2] += wgt * f1.x; acc[3] += wgt * f1.y;
        acc[4] += wgt * f2.x; acc[5] += wgt * f2.y;
        acc[6] += wgt * f3.x; acc[7] += wgt * f3.y;
    }
    // combine the two edge-subgroups (xor 8 stays within each node half)
#pragma unroll
    for (int k = 0; k < 8; k++) acc[k] += __shfl_xor_sync(0xffffffffu, acc[k], 8);
    float* out = (layer == 0) ? g_hout : g_h2;
    // g2=0 lanes write features [8ql,8ql+4), g2=1 lanes write [8ql+4,8ql+8)
    int fo = 8 * ql + 4 * g2;
    float4 bb = *(const float4*)&bg[fo];
    int ai = 4 * g2;
    float4 oo = { fmaxf(acc[ai + 0] + bb.x, 0.f),
                  fmaxf(acc[ai + 1] + bb.y, 0.f),
                  fmaxf(acc[ai + 2] + bb.z, 0.f),
                  fmaxf(acc[ai + 3] + bb.w, 0.f) };
    *(float4*)&out[n * H + fo] = oo;
}

// ---------------- classifier + flag head ----------------
__global__ void k_cls(const float* __restrict__ x,
                      const float* __restrict__ Wc1, const float* __restrict__ bc1,
                      const float* __restrict__ Wc2, const float* __restrict__ bc2,
                      const float* __restrict__ Wh1, const float* __restrict__ bh1,
                      const float* __restrict__ Wh2, const float* __restrict__ bh2,
                      float* __restrict__ out) {
    __shared__ float sW[H][H];
    __shared__ __align__(16) float sht[H][36];
    __shared__ float st[32][H + 1];
    __shared__ float sW2[H][4];
    int t = threadIdx.x;
    int n0 = blockIdx.x * 32;
    for (int i = t; i < H * H; i += 256) sW[i >> 6][i & 63] = Wc1[i];
    if (t < H * 4) sW2[t >> 2][t & 3] = Wc2[t];
    for (int idx = t; idx < 32 * H; idx += 256) {
        int nl = idx >> 6, j = idx & 63;
        sht[j][nl] = g_h2[(n0 + nl) * H + j];
    }
    __syncthreads();

    int w = t >> 5, lane = t & 31;
    float2 bb = *(const float2*)&bc1[2 * lane];
    float a00 = bb.x, a01 = bb.y, a10 = bb.x, a11 = bb.y;
    float a20 = bb.x, a21 = bb.y, a30 = bb.x, a31 = bb.y;
#pragma unroll
    for (int k = 0; k < H; k++) {
        float2 wv = *(const float2*)&sW[k][2 * lane];
        float4 hv = *(const float4*)&sht[k][w * 4];
        a00 += hv.x * wv.x; a01 += hv.x * wv.y;
        a10 += hv.y * wv.x; a11 += hv.y * wv.y;
        a20 += hv.z * wv.x; a21 += hv.z * wv.y;
        a30 += hv.w * wv.x; a31 += hv.w * wv.y;
    }
    int nb = w * 4;
    st[nb + 0][2 * lane] = fmaxf(a00, 0.f); st[nb + 0][2 * lane + 1] = fmaxf(a01, 0.f);
    st[nb + 1][2 * lane] = fmaxf(a10, 0.f); st[nb + 1][2 * lane + 1] = fmaxf(a11, 0.f);
    st[nb + 2][2 * lane] = fmaxf(a20, 0.f); st[nb + 2][2 * lane + 1] = fmaxf(a21, 0.f);
    st[nb + 3][2 * lane] = fmaxf(a30, 0.f); st[nb + 3][2 * lane + 1] = fmaxf(a31, 0.f);
    __syncthreads();

    if (t < 128) {
        int nl = t >> 2, oj = t & 3;
        int n = n0 + nl;
        float cacc = bc2[oj];
#pragma unroll
        for (int k = 0; k < H; k++) cacc += st[nl][k] * sW2[k][oj];
        float f0 = x[n * 8 + 6], f1 = x[n * 8 + 7];
        float facc = bh2[oj];
#pragma unroll
        for (int m = 0; m < 8; m++) {
            float u = fmaxf(f0 * Wh1[m] + f1 * Wh1[8 + m] + bh1[m], 0.f);
            facc += u * Wh2[m * 4 + oj];
        }
        out[n * 4 + oj] = cacc + 0.03f * facc;
    }
}

// ---------------- launch ----------------
extern "C" void kernel_launch(void* const* d_in, const int* in_sizes, int n_in,
                              void* d_out, int out_size) {
    const float* x       = (const float*)d_in[0];
    const int*   ei      = (const int*)  d_in[1];
    const int*   batch   = (const int*)  d_in[2];
    const float* climber = (const float*)d_in[3];
    const float* W_in    = (const float*)d_in[4];
    const float* b_in    = (const float*)d_in[5];
    const float* ln_g    = (const float*)d_in[6];
    const float* ln_b    = (const float*)d_in[7];
    const float* W_c     = (const float*)d_in[8];
    const float* b_c     = (const float*)d_in[9];
    const float* Wf1     = (const float*)d_in[10];
    const float* bf1     = (const float*)d_in[11];
    const float* Wf2     = (const float*)d_in[12];
    const float* bf2     = (const float*)d_in[13];
    const float* Wg1     = (const float*)d_in[14];
    const float* as1     = (const float*)d_in[15];
    const float* ad1     = (const float*)d_in[16];
    const float* bg1     = (const float*)d_in[17];
    const float* Wg2     = (const float*)d_in[18];
    const float* as2     = (const float*)d_in[19];
    const float* ad2     = (const float*)d_in[20];
    const float* bg2     = (const float*)d_in[21];
    const float* Wc1     = (const float*)d_in[22];
    const float* bc1     = (const float*)d_in[23];
    const float* Wc2     = (const float*)d_in[24];
    const float* bc2     = (const float*)d_in[25];
    const float* Wh1     = (const float*)d_in[26];
    const float* bh1     = (const float*)d_in[27];
    const float* Wh2     = (const float*)d_in[28];
    const float* bh2     = (const float*)d_in[29];
    float* out = (float*)d_out;

    k_climber_zero<<<NG + (NN + 127) / 128, 128>>>(climber, ln_g, ln_b, W_c, b_c,
                                                   Wf1, bf1, Wf2, bf2);
    k_fill<<<(TOT_E + 255) / 256, 256>>>(ei);

    k_film_z<<<NN / 32, 256>>>(0, x, batch, W_in, b_in, Wg1, as1, ad1);
    k_softmax<<<(NN + 255) / 256, 256>>>();
    k_gatherB<<<(NN / 2 * 32 + 255) / 256, 256>>>(0, bg1);

    k_film_z<<<NN / 32, 256>>>(1, x, batch, W_in, b_in, Wg2, as2, ad2);
    k_softmax<<<(NN + 255) / 256, 256>>>();
    k_gatherB<<<(NN / 2 * 32 + 255) / 256, 256>>>(1, bg2);

    k_cls<<<NN / 32, 256>>>(x, Wc1, bc1, Wc2, bc2, Wh1, bh1, Wh2, bh2, out);
}

// round 9
// speedup vs baseline: 1.2634x; 1.2634x over previous
#include <cuda_runtime.h>
#include <cuda_fp16.h>

#define NN 100000
#define NE 1200000
#define NG 1000
#define H  64
#define TOT_E (NE + NN)
#define SLOT 64

// ---------------- scratch (no allocations allowed) ----------------
__device__ __half g_zh[NN * H];    // z in fp16 (values only; logits stay fp32)
__device__ float g_hout[NN * H];   // gat1 output / film2 input
__device__ float g_h2[NN * H];     // gat2 output / cls input
__device__ float g_zs[NN];
__device__ float g_zd[NN];
__device__ int   g_cnt[NN];
__device__ int   g_col2[NN * SLOT];
__device__ float g_gamma1[NG * H], g_beta1[NG * H];
__device__ float g_gamma2[NG * H], g_beta2[NG * H];

// ---------------- climber MLP + FiLM params, fused with g_cnt zeroing ----------------
__global__ void k_climber_zero(const float* __restrict__ climber,
                               const float* __restrict__ ln_g, const float* __restrict__ ln_b,
                               const float* __restrict__ W_c,  const float* __restrict__ b_c,
                               const float* __restrict__ Wf1,  const float* __restrict__ bf1,
                               const float* __restrict__ Wf2,  const float* __restrict__ bf2) {
    if (blockIdx.x >= NG) {
        int i = (blockIdx.x - NG) * 128 + threadIdx.x;
        if (i < NN) g_cnt[i] = 0;
        return;
    }
    __shared__ float cv[6], cn[6], c_sh[H];
    int g = blockIdx.x;
    int t = threadIdx.x;
    if (t < 6) cv[t] = climber[g * 6 + t];
    __syncthreads();
    float mu = (cv[0] + cv[1] + cv[2] + cv[3] + cv[4] + cv[5]) * (1.0f / 6.0f);
    float var = 0.f;
#pragma unroll
    for (int k = 0; k < 6; k++) { float d = cv[k] - mu; var += d * d; }
    var *= (1.0f / 6.0f);
    float rstd = rsqrtf(var + 1e-5f);
    if (t < 6) cn[t] = (cv[t] - mu) * rstd * ln_g[t] + ln_b[t];
    __syncthreads();
    if (t < H) {
        float a = b_c[t];
#pragma unroll
        for (int k = 0; k < 6; k++) a += cn[k] * W_c[k * H + t];
        c_sh[t] = fmaxf(a, 0.f);
    }
    __syncthreads();
    float a1 = bf1[t], a2 = bf2[t];
    for (int k = 0; k < H; k++) {
        float cc = c_sh[k];
        a1 += cc * Wf1[k * 128 + t];
        a2 += cc * Wf2[k * 128 + t];
    }
    if (t < H) { g_gamma1[g * H + t] = a1; g_gamma2[g * H + t] = a2; }
    else       { g_beta1[g * H + t - H] = a1; g_beta2[g * H + t - H] = a2; }
}

// ---------------- direct padded-adjacency fill (count == placement) ----------------
__global__ void k_fill(const int* __restrict__ ei) {
    int idx = blockIdx.x * blockDim.x + threadIdx.x;
    if (idx >= TOT_E) return;
    int s, d;
    if (idx < NE) { s = ei[idx]; d = ei[NE + idx]; }
    else          { s = d = idx - NE; }
    int pos = atomicAdd(&g_cnt[d], 1);
    if (pos < SLOT) g_col2[d * SLOT + pos] = s;
}

// ---------------- FiLM (+ fused input proj for layer 0) + z = hf@Wg, zs, zd ----------------
// 32 nodes per block, 4 nodes per warp, 2 outputs per lane
__global__ void k_film_z(int layer, const float* __restrict__ x,
                         const int* __restrict__ batch,
                         const float* __restrict__ Win, const float* __restrict__ bin,
                         const float* __restrict__ Wg,
                         const float* __restrict__ a_s,
                         const float* __restrict__ a_d) {
    __shared__ float sW[H][H];      // sW[k][j]
    __shared__ __align__(16) float sht[H][36];
    __shared__ float sWin[6][H];
    __shared__ float sbin[H];
    __shared__ float sx[32][8];
    __shared__ int   sb[32];
    int t = threadIdx.x;
    int n0 = blockIdx.x * 32;
    for (int i = t; i < H * H; i += 256) sW[i >> 6][i & 63] = Wg[i];
    if (t < 32) sb[t] = batch[n0 + t];
    if (layer == 0) {
        for (int i = t; i < 6 * H; i += 256) sWin[i >> 6][i & 63] = Win[i];
        if (t < H) sbin[t] = bin[t];
        sx[t >> 3][t & 7] = x[(n0 + (t >> 3)) * 8 + (t & 7)];
    }
    __syncthreads();
    const float* gam = (layer == 0) ? g_gamma1 : g_gamma2;
    const float* bet = (layer == 0) ? g_beta1 : g_beta2;
    for (int idx = t; idx < 32 * H; idx += 256) {
        int nl = idx >> 6, j = idx & 63;
        int n = n0 + nl;
        int b = sb[nl];
        float hv;
        if (layer == 0) {
            hv = sbin[j];
#pragma unroll
            for (int k = 0; k < 6; k++) hv += sx[nl][k] * sWin[k][j];
        } else {
            hv = g_hout[n * H + j];
        }
        sht[j][nl] = hv * (1.f + gam[b * H + j]) + bet[b * H + j];
    }
    __syncthreads();

    int w = t >> 5, lane = t & 31;
    float a00 = 0.f, a01 = 0.f, a10 = 0.f, a11 = 0.f;
    float a20 = 0.f, a21 = 0.f, a30 = 0.f, a31 = 0.f;
#pragma unroll
    for (int k = 0; k < H; k++) {
        float2 wv = *(const float2*)&sW[k][2 * lane];
        float4 hv = *(const float4*)&sht[k][w * 4];
        a00 += hv.x * wv.x; a01 += hv.x * wv.y;
        a10 += hv.y * wv.x; a11 += hv.y * wv.y;
        a20 += hv.z * wv.x; a21 += hv.z * wv.y;
        a30 += hv.w * wv.x; a31 += hv.w * wv.y;
    }
    int nb = n0 + w * 4;
    // z stored fp16 (values); logits below stay fp32
    *(__half2*)&g_zh[(nb + 0) * H + 2 * lane] = __floats2half2_rn(a00, a01);
    *(__half2*)&g_zh[(nb + 1) * H + 2 * lane] = __floats2half2_rn(a10, a11);
    *(__half2*)&g_zh[(nb + 2) * H + 2 * lane] = __floats2half2_rn(a20, a21);
    *(__half2*)&g_zh[(nb + 3) * H + 2 * lane] = __floats2half2_rn(a30, a31);
    float2 as = *(const float2*)&a_s[2 * lane];
    float2 ad = *(const float2*)&a_d[2 * lane];
    float r0 = a00 * as.x + a01 * as.y, q0 = a00 * ad.x + a01 * ad.y;
    float r1 = a10 * as.x + a11 * as.y, q1 = a10 * ad.x + a11 * ad.y;
    float r2 = a20 * as.x + a21 * as.y, q2 = a20 * ad.x + a21 * ad.y;
    float r3 = a30 * as.x + a31 * as.y, q3 = a30 * ad.x + a31 * ad.y;
#pragma unroll
    for (int o = 16; o; o >>= 1) {
        r0 += __shfl_xor_sync(0xffffffffu, r0, o);
        r1 += __shfl_xor_sync(0xffffffffu, r1, o);
        r2 += __shfl_xor_sync(0xffffffffu, r2, o);
        r3 += __shfl_xor_sync(0xffffffffu, r3, o);
        q0 += __shfl_xor_sync(0xffffffffu, q0, o);
        q1 += __shfl_xor_sync(0xffffffffu, q1, o);
        q2 += __shfl_xor_sync(0xffffffffu, q2, o);
        q3 += __shfl_xor_sync(0xffffffffu, q3, o);
    }
    if (lane == 0) {
        g_zs[nb + 0] = r0; g_zd[nb + 0] = q0;
        g_zs[nb + 1] = r1; g_zd[nb + 1] = q1;
        g_zs[nb + 2] = r2; g_zd[nb + 2] = q2;
        g_zs[nb + 3] = r3; g_zd[nb + 3] = q3;
    }
}

// ---------------- fused GAT: warp per 2 nodes; warp-coop softmax -> smem -> gather --------
// Phase 1: each half-warp computes its node's normalized weights (16 slots/round,
// register-held logits, shfl max/sum) into smem; offsets premultiplied.
// Phase 2: 8-lane groups gather full 128B fp16 z rows; wgt/off via broadcast LDS;
// padding slots carry wgt=0/off=0 so the loop has no predicates.
__global__ void k_gat_ws(int layer, const float* __restrict__ bg) {
    __shared__ float swgt[8][2][SLOT];
    __shared__ int   soff[8][2][SLOT];
    int gw = (blockIdx.x * blockDim.x + threadIdx.x) >> 5;
    int wb = threadIdx.x >> 5;
    int lane = threadIdx.x & 31;
    int nl = lane >> 4, hl = lane & 15;
    int n = gw * 2 + nl;
    if (n >= NN) return;               // NN even: whole warp exits together
    int cnt = min(g_cnt[n], SLOT);
    int cmax = max(cnt, __shfl_xor_sync(0xffffffffu, cnt, 16));  // warp-uniform
    int rounds = (cmax + 15) >> 4;
    const int* __restrict__ cols = g_col2 + n * SLOT;
    float zdd = g_zd[n];
    float ev0 = -1e30f, ev1 = -1e30f, ev2 = -1e30f, ev3 = -1e30f;
#define LOGIT(r, ev)                                            \
    if (r < rounds) {                                           \
        int i = r * 16 + hl;                                    \
        int of = 0;                                             \
        if (i < cnt) {                                          \
            int s = cols[i];                                    \
            float tv = g_zs[s] + zdd;                           \
            ev = fmaxf(tv, 0.2f * tv);                          \
            of = s << 6;                                        \
        }                                                       \
        soff[wb][nl][i] = of;                                   \
    }
    LOGIT(0, ev0) LOGIT(1, ev1) LOGIT(2, ev2) LOGIT(3, ev3)
#undef LOGIT
    float m = fmaxf(fmaxf(ev0, ev1), fmaxf(ev2, ev3));
#pragma unroll
    for (int o = 8; o; o >>= 1) m = fmaxf(m, __shfl_xor_sync(0xffffffffu, m, o));
    float w0 = __expf(ev0 - m), w1 = __expf(ev1 - m);
    float w2 = __expf(ev2 - m), w3 = __expf(ev3 - m);
    float sum = (w0 + w1) + (w2 + w3);
#pragma unroll
    for (int o = 8; o; o >>= 1) sum += __shfl_xor_sync(0xffffffffu, sum, o);
    float invs = 1.f / (sum + 1e-16f);
    if (0 < rounds) swgt[wb][nl][hl]      = w0 * invs;
    if (1 < rounds) swgt[wb][nl][16 + hl] = w1 * invs;
    if (2 < rounds) swgt[wb][nl][32 + hl] = w2 * invs;
    if (3 < rounds) swgt[wb][nl][48 + hl] = w3 * invs;
    __syncwarp();

    // phase 2: weighted gather
    int g2 = (lane >> 3) & 1, ql = lane & 7;
    int trips = (cmax + 1) >> 1;
    const __half* __restrict__ zbase = g_zh + 8 * ql;
    float acc[8] = {0.f, 0.f, 0.f, 0.f, 0.f, 0.f, 0.f, 0.f};
#pragma unroll 2
    for (int j = 0; j < trips; j++) {
        int i = 2 * j + g2;            // i <= cmax <= rounds*16 slots filled
        float wgt = swgt[wb][nl][i];
        int   of  = soff[wb][nl][i];
        float4 raw = *(const float4*)(zbase + of);
        const __half2* hp = (const __half2*)&raw;
        float2 f0 = __half22float2(hp[0]);
        float2 f1 = __half22float2(hp[1]);
        float2 f2 = __half22float2(hp[2]);
        float2 f3 = __half22float2(hp[3]);
        acc[0] += wgt * f0.x; acc[1] += wgt * f0.y;
        acc[2] += wgt * f1.x; acc[3] += wgt * f1.y;
        acc[4] += wgt * f2.x; acc[5] += wgt * f2.y;
        acc[6] += wgt * f3.x; acc[7] += wgt * f3.y;
    }
    // combine the two edge-subgroups (xor 8 stays within each node half)
#pragma unroll
    for (int k = 0; k < 8; k++) acc[k] += __shfl_xor_sync(0xffffffffu, acc[k], 8);
    float* out = (layer == 0) ? g_hout : g_h2;
    int fo = 8 * ql + 4 * g2;
    float4 bb = *(const float4*)&bg[fo];
    int ai = 4 * g2;
    float4 oo = { fmaxf(acc[ai + 0] + bb.x, 0.f),
                  fmaxf(acc[ai + 1] + bb.y, 0.f),
                  fmaxf(acc[ai + 2] + bb.z, 0.f),
                  fmaxf(acc[ai + 3] + bb.w, 0.f) };
    *(float4*)&out[n * H + fo] = oo;
}

// ---------------- classifier + flag head ----------------
__global__ void k_cls(const float* __restrict__ x,
                      const float* __restrict__ Wc1, const float* __restrict__ bc1,
                      const float* __restrict__ Wc2, const float* __restrict__ bc2,
                      const float* __restrict__ Wh1, const float* __restrict__ bh1,
                      const float* __restrict__ Wh2, const float* __restrict__ bh2,
                      float* __restrict__ out) {
    __shared__ float sW[H][H];
    __shared__ __align__(16) float sht[H][36];
    __shared__ float st[32][H + 1];
    __shared__ float sW2[H][4];
    int t = threadIdx.x;
    int n0 = blockIdx.x * 32;
    for (int i = t; i < H * H; i += 256) sW[i >> 6][i & 63] = Wc1[i];
    if (t < H * 4) sW2[t >> 2][t & 3] = Wc2[t];
    for (int idx = t; idx < 32 * H; idx += 256) {
        int nl = idx >> 6, j = idx & 63;
        sht[j][nl] = g_h2[(n0 + nl) * H + j];
    }
    __syncthreads();

    int w = t >> 5, lane = t & 31;
    float2 bb = *(const float2*)&bc1[2 * lane];
    float a00 = bb.x, a01 = bb.y, a10 = bb.x, a11 = bb.y;
    float a20 = bb.x, a21 = bb.y, a30 = bb.x, a31 = bb.y;
#pragma unroll
    for (int k = 0; k < H; k++) {
        float2 wv = *(const float2*)&sW[k][2 * lane];
        float4 hv = *(const float4*)&sht[k][w * 4];
        a00 += hv.x * wv.x; a01 += hv.x * wv.y;
        a10 += hv.y * wv.x; a11 += hv.y * wv.y;
        a20 += hv.z * wv.x; a21 += hv.z * wv.y;
        a30 += hv.w * wv.x; a31 += hv.w * wv.y;
    }
    int nb = w * 4;
    st[nb + 0][2 * lane] = fmaxf(a00, 0.f); st[nb + 0][2 * lane + 1] = fmaxf(a01, 0.f);
    st[nb + 1][2 * lane] = fmaxf(a10, 0.f); st[nb + 1][2 * lane + 1] = fmaxf(a11, 0.f);
    st[nb + 2][2 * lane] = fmaxf(a20, 0.f); st[nb + 2][2 * lane + 1] = fmaxf(a21, 0.f);
    st[nb + 3][2 * lane] = fmaxf(a30, 0.f); st[nb + 3][2 * lane + 1] = fmaxf(a31, 0.f);
    __syncthreads();

    if (t < 128) {
        int nl = t >> 2, oj = t & 3;
        int n = n0 + nl;
        float cacc = bc2[oj];
#pragma unroll
        for (int k = 0; k < H; k++) cacc += st[nl][k] * sW2[k][oj];
        float f0 = x[n * 8 + 6], f1 = x[n * 8 + 7];
        float facc = bh2[oj];
#pragma unroll
        for (int m = 0; m < 8; m++) {
            float u = fmaxf(f0 * Wh1[m] + f1 * Wh1[8 + m] + bh1[m], 0.f);
            facc += u * Wh2[m * 4 + oj];
        }
        out[n * 4 + oj] = cacc + 0.03f * facc;
    }
}

// ---------------- launch ----------------
extern "C" void kernel_launch(void* const* d_in, const int* in_sizes, int n_in,
                              void* d_out, int out_size) {
    const float* x       = (const float*)d_in[0];
    const int*   ei      = (const int*)  d_in[1];
    const int*   batch   = (const int*)  d_in[2];
    const float* climber = (const float*)d_in[3];
    const float* W_in    = (const float*)d_in[4];
    const float* b_in    = (const float*)d_in[5];
    const float* ln_g    = (const float*)d_in[6];
    const float* ln_b    = (const float*)d_in[7];
    const float* W_c     = (const float*)d_in[8];
    const float* b_c     = (const float*)d_in[9];
    const float* Wf1     = (const float*)d_in[10];
    const float* bf1     = (const float*)d_in[11];
    const float* Wf2     = (const float*)d_in[12];
    const float* bf2     = (const float*)d_in[13];
    const float* Wg1     = (const float*)d_in[14];
    const float* as1     = (const float*)d_in[15];
    const float* ad1     = (const float*)d_in[16];
    const float* bg1     = (const float*)d_in[17];
    const float* Wg2     = (const float*)d_in[18];
    const float* as2     = (const float*)d_in[19];
    const float* ad2     = (const float*)d_in[20];
    const float* bg2     = (const float*)d_in[21];
    const float* Wc1     = (const float*)d_in[22];
    const float* bc1     = (const float*)d_in[23];
    const float* Wc2     = (const float*)d_in[24];
    const float* bc2     = (const float*)d_in[25];
    const float* Wh1     = (const float*)d_in[26];
    const float* bh1     = (const float*)d_in[27];
    const float* Wh2     = (const float*)d_in[28];
    const float* bh2     = (const float*)d_in[29];
    float* out = (float*)d_out;

    k_climber_zero<<<NG + (NN + 127) / 128, 128>>>(climber, ln_g, ln_b, W_c, b_c,
                                                   Wf1, bf1, Wf2, bf2);
    k_fill<<<(TOT_E + 255) / 256, 256>>>(ei);

    k_film_z<<<NN / 32, 256>>>(0, x, batch, W_in, b_in, Wg1, as1, ad1);
    k_gat_ws<<<NN / 16, 256>>>(0, bg1);

    k_film_z<<<NN / 32, 256>>>(1, x, batch, W_in, b_in, Wg2, as2, ad2);
    k_gat_ws<<<NN / 16, 256>>>(1, bg2);

    k_cls<<<NN / 32, 256>>>(x, Wc1, bc1, Wc2, bc2, Wh1, bh1, Wh2, bh2, out);
}

// round 11
// speedup vs baseline: 1.4604x; 1.1560x over previous
#include <cuda_runtime.h>
#include <cuda_fp16.h>

#define NN 100000
#define NE 1200000
#define NG 1000
#define H  64
#define TOT_E (NE + NN)
#define SLOT 64
#define NZB  ((NN + 127) / 128)

// ---------------- scratch (no allocations allowed) ----------------
__device__ __half g_zh[NN * H];    // z in fp16 (values only; logits stay fp32)
__device__ float g_hout[NN * H];   // gat1 output / film2 input
__device__ float g_h2[NN * H];     // gat2 output / cls input
__device__ float g_zs[NN];
__device__ float g_zd[NN];
__device__ float g_vs[2][H], g_vd[2][H];  // Wg @ a_src, Wg @ a_dst (fp32, exact logits)
__device__ int   g_cnt[NN];
__device__ int   g_col2[NN * SLOT];
__device__ float g_gamma1[NG * H], g_beta1[NG * H];
__device__ float g_gamma2[NG * H], g_beta2[NG * H];

__device__ __forceinline__ unsigned smem_u32(const void* p) {
    return (unsigned)__cvta_generic_to_shared(p);
}

#define LDSM_X4(r0, r1, r2, r3, addr)                                          \
    asm volatile("ldmatrix.sync.aligned.m8n8.x4.shared.b16 {%0,%1,%2,%3}, [%4];" \
                 : "=r"(r0), "=r"(r1), "=r"(r2), "=r"(r3) : "r"(addr))
#define LDSM_X4_T(r0, r1, r2, r3, addr)                                        \
    asm volatile("ldmatrix.sync.aligned.m8n8.x4.trans.shared.b16 {%0,%1,%2,%3}, [%4];" \
                 : "=r"(r0), "=r"(r1), "=r"(r2), "=r"(r3) : "r"(addr))
#define MMA16816(c, a0, a1, a2, a3, b0, b1)                                    \
    asm volatile("mma.sync.aligned.m16n8k16.row.col.f32.f16.f16.f32 "          \
                 "{%0,%1,%2,%3}, {%4,%5,%6,%7}, {%8,%9}, {%0,%1,%2,%3};"       \
                 : "+f"(c[0]), "+f"(c[1]), "+f"(c[2]), "+f"(c[3])              \
                 : "r"(a0), "r"(a1), "r"(a2), "r"(a3), "r"(b0), "r"(b1))

// ---------------- climber MLP + FiLM params + g_cnt zeroing + attn-vector prep ----------
// v-prep: TWO blocks x 128 threads (2 vectors per block) — 4 vectors total.
__global__ void k_climber_zero(const float* __restrict__ climber,
                               const float* __restrict__ ln_g, const float* __restrict__ ln_b,
                               const float* __restrict__ W_c,  const float* __restrict__ b_c,
                               const float* __restrict__ Wf1,  const float* __restrict__ bf1,
                               const float* __restrict__ Wf2,  const float* __restrict__ bf2,
                               const float* __restrict__ Wg1,  const float* __restrict__ as1,
                               const float* __restrict__ ad1,
                               const float* __restrict__ Wg2,  const float* __restrict__ as2,
                               const float* __restrict__ ad2) {
    if (blockIdx.x >= NG + NZB) {
        // v = Wg @ a : which in {0:Wg1*as1, 1:Wg1*ad1, 2:Wg2*as2, 3:Wg2*ad2}
        int which = (blockIdx.x - (NG + NZB)) * 2 + (threadIdx.x >> 6);
        int k = threadIdx.x & 63;
        const float* W = (which < 2) ? Wg1 : Wg2;
        const float* a = (which & 1) ? ((which < 2) ? ad1 : ad2)
                                     : ((which < 2) ? as1 : as2);
        float v = 0.f;
#pragma unroll 8
        for (int j = 0; j < H; j++) v += W[k * H + j] * a[j];
        if (which & 1) g_vd[which >> 1][k] = v;
        else           g_vs[which >> 1][k] = v;
        return;
    }
    if (blockIdx.x >= NG) {
        int i = (blockIdx.x - NG) * 128 + threadIdx.x;
        if (i < NN) g_cnt[i] = 0;
        return;
    }
    __shared__ float cv[6], cn[6], c_sh[H];
    int g = blockIdx.x;
    int t = threadIdx.x;
    if (t < 6) cv[t] = climber[g * 6 + t];
    __syncthreads();
    float mu = (cv[0] + cv[1] + cv[2] + cv[3] + cv[4] + cv[5]) * (1.0f / 6.0f);
    float var = 0.f;
#pragma unroll
    for (int k = 0; k < 6; k++) { float d = cv[k] - mu; var += d * d; }
    var *= (1.0f / 6.0f);
    float rstd = rsqrtf(var + 1e-5f);
    if (t < 6) cn[t] = (cv[t] - mu) * rstd * ln_g[t] + ln_b[t];
    __syncthreads();
    if (t < H) {
        float a = b_c[t];
#pragma unroll
        for (int k = 0; k < 6; k++) a += cn[k] * W_c[k * H + t];
        c_sh[t] = fmaxf(a, 0.f);
    }
    __syncthreads();
    float a1 = bf1[t], a2 = bf2[t];
    for (int k = 0; k < H; k++) {
        float cc = c_sh[k];
        a1 += cc * Wf1[k * 128 + t];
        a2 += cc * Wf2[k * 128 + t];
    }
    if (t < H) { g_gamma1[g * H + t] = a1; g_gamma2[g * H + t] = a2; }
    else       { g_beta1[g * H + t - H] = a1; g_beta2[g * H + t - H] = a2; }
}

// ---------------- direct padded-adjacency fill (count == placement) ----------------
__global__ void k_fill(const int* __restrict__ ei) {
    int idx = blockIdx.x * blockDim.x + threadIdx.x;
    if (idx >= TOT_E) return;
    int s, d;
    if (idx < NE) { s = ei[idx]; d = ei[NE + idx]; }
    else          { s = d = idx - NE; }
    int pos = atomicAdd(&g_cnt[d], 1);
    if (pos < SLOT) g_col2[d * SLOT + pos] = s;
}

// ---------------- FiLM (+ input proj) + tensor-core z GEMM + exact zs/zd ----------------
// 32 nodes/block. Stage1: 8 threads/node compute fp32 filmed hf, fp32 zs/zd via
// precomputed v_s/v_d, store hf fp16 to smem A. GEMM: 8 warps, mma.m16n8k16,
// fp32 accum to smem C. Epilogue: fp16 z out.
__global__ void k_film_z(int layer, const float* __restrict__ x,
                         const int* __restrict__ batch,
                         const float* __restrict__ Win, const float* __restrict__ bin,
                         const float* __restrict__ Wg) {
    __shared__ __half sW[H][72];
    __shared__ __half sA[32][72];
    __shared__ float  sC[32][68];
    __shared__ float  sWin[6][H];
    __shared__ float  sbin[H];
    __shared__ float  sx[32][8];
    __shared__ float  svs[H], svd[H];
    int t = threadIdx.x;
    int n0 = blockIdx.x * 32;
    for (int i = t; i < H * H; i += 256) sW[i >> 6][i & 63] = __float2half(Wg[i]);
    if (t < H) { svs[t] = g_vs[layer][t]; svd[t] = g_vd[layer][t]; }
    if (layer == 0) {
        for (int i = t; i < 6 * H; i += 256) sWin[i >> 6][i & 63] = Win[i];
        if (t >= 64 && t < 128) sbin[t - 64] = bin[t - 64];
        sx[t >> 3][t & 7] = x[(n0 + (t >> 3)) * 8 + (t & 7)];
    }
    __syncthreads();

    // ---- stage 1: filmed hf (fp32), zs/zd (fp32), A tile (fp16) ----
    int nl = t >> 3, jb = (t & 7) * 8;
    int n = n0 + nl;
    int b = batch[n];
    const float* gam = ((layer == 0) ? g_gamma1 : g_gamma2) + b * H + jb;
    const float* bet = ((layer == 0) ? g_beta1  : g_beta2 ) + b * H + jb;
    float hf[8];
    if (layer == 0) {
        float xr[6];
#pragma unroll
        for (int k = 0; k < 6; k++) xr[k] = sx[nl][k];
#pragma unroll
        for (int j = 0; j < 8; j++) {
            float v = sbin[jb + j];
#pragma unroll
            for (int k = 0; k < 6; k++) v += xr[k] * sWin[k][jb + j];
            hf[j] = v;
        }
    } else {
        float4 h0 = *(const float4*)&g_hout[n * H + jb];
        float4 h1 = *(const float4*)&g_hout[n * H + jb + 4];
        hf[0] = h0.x; hf[1] = h0.y; hf[2] = h0.z; hf[3] = h0.w;
        hf[4] = h1.x; hf[5] = h1.y; hf[6] = h1.z; hf[7] = h1.w;
    }
    float4 ga = *(const float4*)&gam[0];
    float4 gb = *(const float4*)&gam[4];
    float4 ba = *(const float4*)&bet[0];
    float4 bb = *(const float4*)&bet[4];
    hf[0] = hf[0] * (1.f + ga.x) + ba.x;
    hf[1] = hf[1] * (1.f + ga.y) + ba.y;
    hf[2] = hf[2] * (1.f + ga.z) + ba.z;
    hf[3] = hf[3] * (1.f + ga.w) + ba.w;
    hf[4] = hf[4] * (1.f + gb.x) + bb.x;
    hf[5] = hf[5] * (1.f + gb.y) + bb.y;
    hf[6] = hf[6] * (1.f + gb.z) + bb.z;
    hf[7] = hf[7] * (1.f + gb.w) + bb.w;
    float ps = 0.f, pd = 0.f;
#pragma unroll
    for (int j = 0; j < 8; j++) { ps += hf[j] * svs[jb + j]; pd += hf[j] * svd[jb + j]; }
#pragma unroll
    for (int o = 4; o; o >>= 1) {
        ps += __shfl_xor_sync(0xffffffffu, ps, o);
        pd += __shfl_xor_sync(0xffffffffu, pd, o);
    }
    if ((t & 7) == 0) { g_zs[n] = ps; g_zd[n] = pd; }
    *(__half2*)&sA[nl][jb + 0] = __floats2half2_rn(hf[0], hf[1]);
    *(__half2*)&sA[nl][jb + 2] = __floats2half2_rn(hf[2], hf[3]);
    *(__half2*)&sA[nl][jb + 4] = __floats2half2_rn(hf[4], hf[5]);
    *(__half2*)&sA[nl][jb + 6] = __floats2half2_rn(hf[6], hf[7]);
    __syncthreads();

    // ---- GEMM: C[32x64] = A[32x64] x W[64x64], warp tiles M16 x N16 ----
    int w = t >> 5, l = t & 31;
    int mw = w >> 2, nw = w & 3;
    float c0[4] = {0.f, 0.f, 0.f, 0.f};
    float c1[4] = {0.f, 0.f, 0.f, 0.f};
    int arow = mw * 16 + (l & 15);
    int acol = (l >> 4) * 8;
    int brow = (l & 7) + ((l >> 3) & 1) * 8;
    int bcol = nw * 16 + (l >> 4) * 8;
#pragma unroll
    for (int kk = 0; kk < 4; kk++) {
        unsigned a0, a1, a2, a3, b0, b1, b2, b3;
        LDSM_X4(a0, a1, a2, a3, smem_u32(&sA[arow][kk * 16 + acol]));
        LDSM_X4_T(b0, b1, b2, b3, smem_u32(&sW[kk * 16 + brow][bcol]));
        MMA16816(c0, a0, a1, a2, a3, b0, b1);
        MMA16816(c1, a0, a1, a2, a3, b2, b3);
    }
    int row0 = mw * 16 + (l >> 2);
    int col0 = nw * 16 + (l & 3) * 2;
    sC[row0][col0]         = c0[0]; sC[row0][col0 + 1]     = c0[1];
    sC[row0 + 8][col0]     = c0[2]; sC[row0 + 8][col0 + 1] = c0[3];
    sC[row0][col0 + 8]     = c1[0]; sC[row0][col0 + 9]     = c1[1];
    sC[row0 + 8][col0 + 8] = c1[2]; sC[row0 + 8][col0 + 9] = c1[3];
    __syncthreads();

    // ---- epilogue: z -> fp16 global (coalesced) ----
    float4 z0 = *(float4*)&sC[nl][jb];
    float4 z1 = *(float4*)&sC[nl][jb + 4];
    __align__(16) __half ho[8];
    ho[0] = __float2half(z0.x); ho[1] = __float2half(z0.y);
    ho[2] = __float2half(z0.z); ho[3] = __float2half(z0.w);
    ho[4] = __float2half(z1.x); ho[5] = __float2half(z1.y);
    ho[6] = __float2half(z1.z); ho[7] = __float2half(z1.w);
    *(float4*)&g_zh[n * H + jb] = *(float4*)ho;
}

// ---------------- fused GAT: warp per 2 nodes; warp-coop softmax -> smem -> gather --------
__global__ void k_gat_ws(int layer, const float* __restrict__ bg) {
    __shared__ float swgt[8][2][SLOT];
    __shared__ int   soff[8][2][SLOT];
    int gw = (blockIdx.x * blockDim.x + threadIdx.x) >> 5;
    int wb = threadIdx.x >> 5;
    int lane = threadIdx.x & 31;
    int nl = lane >> 4, hl = lane & 15;
    int n = gw * 2 + nl;
    if (n >= NN) return;               // NN even: whole warp exits together
    int cnt = min(g_cnt[n], SLOT);
    int cmax = max(cnt, __shfl_xor_sync(0xffffffffu, cnt, 16));  // warp-uniform
    int rounds = (cmax + 15) >> 4;
    const int* __restrict__ cols = g_col2 + n * SLOT;
    float zdd = g_zd[n];
    float ev0 = -1e30f, ev1 = -1e30f, ev2 = -1e30f, ev3 = -1e30f;
#define LOGIT(r, ev)                                            \
    if (r < rounds) {                                           \
        int i = r * 16 + hl;                                    \
        int of = 0;                                             \
        if (i < cnt) {                                          \
            int s = cols[i];                                    \
            float tv = g_zs[s] + zdd;                           \
            ev = fmaxf(tv, 0.2f * tv);                          \
            of = s << 6;                                        \
        }                                                       \
        soff[wb][nl][i] = of;                                   \
    }
    LOGIT(0, ev0) LOGIT(1, ev1) LOGIT(2, ev2) LOGIT(3, ev3)
#undef LOGIT
    float m = fmaxf(fmaxf(ev0, ev1), fmaxf(ev2, ev3));
#pragma unroll
    for (int o = 8; o; o >>= 1) m = fmaxf(m, __shfl_xor_sync(0xffffffffu, m, o));
    float w0 = __expf(ev0 - m), w1 = __expf(ev1 - m);
    float w2 = __expf(ev2 - m), w3 = __expf(ev3 - m);
    float sum = (w0 + w1) + (w2 + w3);
#pragma unroll
    for (int o = 8; o; o >>= 1) sum += __shfl_xor_sync(0xffffffffu, sum, o);
    float invs = 1.f / (sum + 1e-16f);
    if (0 < rounds) swgt[wb][nl][hl]      = w0 * invs;
    if (1 < rounds) swgt[wb][nl][16 + hl] = w1 * invs;
    if (2 < rounds) swgt[wb][nl][32 + hl] = w2 * invs;
    if (3 < rounds) swgt[wb][nl][48 + hl] = w3 * invs;
    __syncwarp();

    // phase 2: weighted gather
    int g2 = (lane >> 3) & 1, ql = lane & 7;
    int trips = (cmax + 1) >> 1;
    const __half* __restrict__ zbase = g_zh + 8 * ql;
    float acc[8] = {0.f, 0.f, 0.f, 0.f, 0.f, 0.f, 0.f, 0.f};
#pragma unroll 2
    for (int j = 0; j < trips; j++) {
        int i = 2 * j + g2;
        float wgt = swgt[wb][nl][i];
        int   of  = soff[wb][nl][i];
        float4 raw = *(const float4*)(zbase + of);
        const __half2* hp = (const __half2*)&raw;
        float2 f0 = __half22float2(hp[0]);
        float2 f1 = __half22float2(hp[1]);
        float2 f2 = __half22float2(hp[2]);
        float2 f3 = __half22float2(hp[3]);
        acc[0] += wgt * f0.x; acc[1] += wgt * f0.y;
        acc[2] += wgt * f1.x; acc[3] += wgt * f1.y;
        acc[4] += wgt * f2.x; acc[5] += wgt * f2.y;
        acc[6] += wgt * f3.x; acc[7] += wgt * f3.y;
    }
#pragma unroll
    for (int k = 0; k < 8; k++) acc[k] += __shfl_xor_sync(0xffffffffu, acc[k], 8);
    float* out = (layer == 0) ? g_hout : g_h2;
    int fo = 8 * ql + 4 * g2;
    float4 bv = *(const float4*)&bg[fo];
    int ai = 4 * g2;
    float4 oo = { fmaxf(acc[ai + 0] + bv.x, 0.f),
                  fmaxf(acc[ai + 1] + bv.y, 0.f),
                  fmaxf(acc[ai + 2] + bv.z, 0.f),
                  fmaxf(acc[ai + 3] + bv.w, 0.f) };
    *(float4*)&out[n * H + fo] = oo;
}

// ---------------- classifier + flag head ----------------
__global__ void k_cls(const float* __restrict__ x,
                      const float* __restrict__ Wc1, const float* __restrict__ bc1,
                      const float* __restrict__ Wc2, const float* __restrict__ bc2,
                      const float* __restrict__ Wh1, const float* __restrict__ bh1,
                      const float* __restrict__ Wh2, const float* __restrict__ bh2,
                      float* __restrict__ out) {
    __shared__ float sW[H][H];
    __shared__ __align__(16) float sht[H][36];
    __shared__ float st[32][H + 1];
    __shared__ float sW2[H][4];
    int t = threadIdx.x;
    int n0 = blockIdx.x * 32;
    for (int i = t; i < H * H; i += 256) sW[i >> 6][i & 63] = Wc1[i];
    if (t < H * 4) sW2[t >> 2][t & 3] = Wc2[t];
    for (int idx = t; idx < 32 * H; idx += 256) {
        int nl = idx >> 6, j = idx & 63;
        sht[j][nl] = g_h2[(n0 + nl) * H + j];
    }
    __syncthreads();

    int w = t >> 5, lane = t & 31;
    float2 bb = *(const float2*)&bc1[2 * lane];
    float a00 = bb.x, a01 = bb.y, a10 = bb.x, a11 = bb.y;
    float a20 = bb.x, a21 = bb.y, a30 = bb.x, a31 = bb.y;
#pragma unroll
    for (int k = 0; k < H; k++) {
        float2 wv = *(const float2*)&sW[k][2 * lane];
        float4 hv = *(const float4*)&sht[k][w * 4];
        a00 += hv.x * wv.x; a01 += hv.x * wv.y;
        a10 += hv.y * wv.x; a11 += hv.y * wv.y;
        a20 += hv.z * wv.x; a21 += hv.z * wv.y;
        a30 += hv.w * wv.x; a31 += hv.w * wv.y;
    }
    int nb = w * 4;
    st[nb + 0][2 * lane] = fmaxf(a00, 0.f); st[nb + 0][2 * lane + 1] = fmaxf(a01, 0.f);
    st[nb + 1][2 * lane] = fmaxf(a10, 0.f); st[nb + 1][2 * lane + 1] = fmaxf(a11, 0.f);
    st[nb + 2][2 * lane] = fmaxf(a20, 0.f); st[nb + 2][2 * lane + 1] = fmaxf(a21, 0.f);
    st[nb + 3][2 * lane] = fmaxf(a30, 0.f); st[nb + 3][2 * lane + 1] = fmaxf(a31, 0.f);
    __syncthreads();

    if (t < 128) {
        int nl = t >> 2, oj = t & 3;
        int n = n0 + nl;
        float cacc = bc2[oj];
#pragma unroll
        for (int k = 0; k < H; k++) cacc += st[nl][k] * sW2[k][oj];
        float f0 = x[n * 8 + 6], f1 = x[n * 8 + 7];
        float facc = bh2[oj];
#pragma unroll
        for (int m = 0; m < 8; m++) {
            float u = fmaxf(f0 * Wh1[m] + f1 * Wh1[8 + m] + bh1[m], 0.f);
            facc += u * Wh2[m * 4 + oj];
        }
        out[n * 4 + oj] = cacc + 0.03f * facc;
    }
}

// ---------------- launch ----------------
extern "C" void kernel_launch(void* const* d_in, const int* in_sizes, int n_in,
                              void* d_out, int out_size) {
    const float* x       = (const float*)d_in[0];
    const int*   ei      = (const int*)  d_in[1];
    const int*   batch   = (const int*)  d_in[2];
    const float* climber = (const float*)d_in[3];
    const float* W_in    = (const float*)d_in[4];
    const float* b_in    = (const float*)d_in[5];
    const float* ln_g    = (const float*)d_in[6];
    const float* ln_b    = (const float*)d_in[7];
    const float* W_c     = (const float*)d_in[8];
    const float* b_c     = (const float*)d_in[9];
    const float* Wf1     = (const float*)d_in[10];
    const float* bf1     = (const float*)d_in[11];
    const float* Wf2     = (const float*)d_in[12];
    const float* bf2     = (const float*)d_in[13];
    const float* Wg1     = (const float*)d_in[14];
    const float* as1     = (const float*)d_in[15];
    const float* ad1     = (const float*)d_in[16];
    const float* bg1     = (const float*)d_in[17];
    const float* Wg2     = (const float*)d_in[18];
    const float* as2     = (const float*)d_in[19];
    const float* ad2     = (const float*)d_in[20];
    const float* bg2     = (const float*)d_in[21];
    const float* Wc1     = (const float*)d_in[22];
    const float* bc1     = (const float*)d_in[23];
    const float* Wc2     = (const float*)d_in[24];
    const float* bc2     = (const float*)d_in[25];
    const float* Wh1     = (const float*)d_in[26];
    const float* bh1     = (const float*)d_in[27];
    const float* Wh2     = (const float*)d_in[28];
    const float* bh2     = (const float*)d_in[29];
    float* out = (float*)d_out;

    k_climber_zero<<<NG + NZB + 2, 128>>>(climber, ln_g, ln_b, W_c, b_c,
                                          Wf1, bf1, Wf2, bf2,
                                          Wg1, as1, ad1, Wg2, as2, ad2);
    k_fill<<<(TOT_E + 255) / 256, 256>>>(ei);

    k_film_z<<<NN / 32, 256>>>(0, x, batch, W_in, b_in, Wg1);
    k_gat_ws<<<NN / 16, 256>>>(0, bg1);

    k_film_z<<<NN / 32, 256>>>(1, x, batch, W_in, b_in, Wg2);
    k_gat_ws<<<NN / 16, 256>>>(1, bg2);

    k_cls<<<NN / 32, 256>>>(x, Wc1, bc1, Wc2, bc2, Wh1, bh1, Wh2, bh2, out);
}

// round 13
// speedup vs baseline: 1.7622x; 1.2066x over previous
#include <cuda_runtime.h>
#include <cuda_fp16.h>

#define NN 100000
#define NE 1200000
#define NG 1000
#define H  64
#define TOT_E (NE + NN)
#define SLOT 64
#define NZB  ((NN + 127) / 128)

// ---------------- scratch (no allocations allowed) ----------------
__device__ __half g_zh[NN * H];    // z in fp16 (values only; logits stay fp32)
__device__ float g_hout[NN * H];   // gat1 output / film2 input
__device__ float g_h2[NN * H];     // gat2 output / cls input
__device__ float g_zs[NN];
__device__ float g_zd[NN];
__device__ float g_vs[2][H], g_vd[2][H];  // Wg @ a_src, Wg @ a_dst (fp32, exact logits)
__device__ __half g_Wgh[2][H * H];        // fp16 Wg1, Wg2 (prepped once)
__device__ __half g_Wc1h[H * H];          // fp16 Wc1
__device__ int   g_cnt[NN];
__device__ int   g_col2[NN * SLOT];
__device__ float g_gamma1[NG * H], g_beta1[NG * H];
__device__ float g_gamma2[NG * H], g_beta2[NG * H];

__device__ __forceinline__ unsigned smem_u32(const void* p) {
    return (unsigned)__cvta_generic_to_shared(p);
}

#define LDSM_X4(r0, r1, r2, r3, addr)                                          \
    asm volatile("ldmatrix.sync.aligned.m8n8.x4.shared.b16 {%0,%1,%2,%3}, [%4];" \
                 : "=r"(r0), "=r"(r1), "=r"(r2), "=r"(r3) : "r"(addr))
#define LDSM_X4_T(r0, r1, r2, r3, addr)                                        \
    asm volatile("ldmatrix.sync.aligned.m8n8.x4.trans.shared.b16 {%0,%1,%2,%3}, [%4];" \
                 : "=r"(r0), "=r"(r1), "=r"(r2), "=r"(r3) : "r"(addr))
#define MMA16816(c, a0, a1, a2, a3, b0, b1)                                    \
    asm volatile("mma.sync.aligned.m16n8k16.row.col.f32.f16.f16.f32 "          \
                 "{%0,%1,%2,%3}, {%4,%5,%6,%7}, {%8,%9}, {%0,%1,%2,%3};"       \
                 : "+f"(c[0]), "+f"(c[1]), "+f"(c[2]), "+f"(c[3])              \
                 : "r"(a0), "r"(a1), "r"(a2), "r"(a3), "r"(b0), "r"(b1))

// ---------------- prep: climber MLP + FiLM + cnt zero + v vectors + fp16 weights --------
__global__ void k_climber_zero(const float* __restrict__ climber,
                               const float* __restrict__ ln_g, const float* __restrict__ ln_b,
                               const float* __restrict__ W_c,  const float* __restrict__ b_c,
                               const float* __restrict__ Wf1,  const float* __restrict__ bf1,
                               const float* __restrict__ Wf2,  const float* __restrict__ bf2,
                               const float* __restrict__ Wg1,  const float* __restrict__ as1,
                               const float* __restrict__ ad1,
                               const float* __restrict__ Wg2,  const float* __restrict__ as2,
                               const float* __restrict__ ad2,
                               const float* __restrict__ Wc1) {
    int t = threadIdx.x;
    if (blockIdx.x >= NG + NZB + 2) {
        // fp16 weight conversion: one block per matrix
        int which = blockIdx.x - (NG + NZB + 2);   // 0:Wg1 1:Wg2 2:Wc1
        const float* W = (which == 0) ? Wg1 : (which == 1) ? Wg2 : Wc1;
        __half* D = (which == 0) ? g_Wgh[0] : (which == 1) ? g_Wgh[1] : g_Wc1h;
        for (int i = t; i < H * H; i += 128) D[i] = __float2half(W[i]);
        return;
    }
    if (blockIdx.x >= NG + NZB) {
        // v = Wg @ a : which in {0:Wg1*as1, 1:Wg1*ad1, 2:Wg2*as2, 3:Wg2*ad2}
        int which = (blockIdx.x - (NG + NZB)) * 2 + (t >> 6);
        int k = t & 63;
        const float* W = (which < 2) ? Wg1 : Wg2;
        const float* a = (which & 1) ? ((which < 2) ? ad1 : ad2)
                                     : ((which < 2) ? as1 : as2);
        float v = 0.f;
#pragma unroll 8
        for (int j = 0; j < H; j++) v += W[k * H + j] * a[j];
        if (which & 1) g_vd[which >> 1][k] = v;
        else           g_vs[which >> 1][k] = v;
        return;
    }
    if (blockIdx.x >= NG) {
        int i = (blockIdx.x - NG) * 128 + t;
        if (i < NN) g_cnt[i] = 0;
        return;
    }
    __shared__ float cv[6], cn[6], c_sh[H];
    int g = blockIdx.x;
    if (t < 6) cv[t] = climber[g * 6 + t];
    __syncthreads();
    float mu = (cv[0] + cv[1] + cv[2] + cv[3] + cv[4] + cv[5]) * (1.0f / 6.0f);
    float var = 0.f;
#pragma unroll
    for (int k = 0; k < 6; k++) { float d = cv[k] - mu; var += d * d; }
    var *= (1.0f / 6.0f);
    float rstd = rsqrtf(var + 1e-5f);
    if (t < 6) cn[t] = (cv[t] - mu) * rstd * ln_g[t] + ln_b[t];
    __syncthreads();
    if (t < H) {
        float a = b_c[t];
#pragma unroll
        for (int k = 0; k < 6; k++) a += cn[k] * W_c[k * H + t];
        c_sh[t] = fmaxf(a, 0.f);
    }
    __syncthreads();
    float a1 = bf1[t], a2 = bf2[t];
    for (int k = 0; k < H; k++) {
        float cc = c_sh[k];
        a1 += cc * Wf1[k * 128 + t];
        a2 += cc * Wf2[k * 128 + t];
    }
    if (t < H) { g_gamma1[g * H + t] = a1; g_gamma2[g * H + t] = a2; }
    else       { g_beta1[g * H + t - H] = a1; g_beta2[g * H + t - H] = a2; }
}

// ---------------- padded-adjacency fill, 4 edges per thread (MLP=4) ----------------
__global__ void k_fill(const int* __restrict__ ei) {
    int t = blockIdx.x * blockDim.x + threadIdx.x;
    if (t < NE / 4) {
        int4 s4 = ((const int4*)ei)[t];
        int4 d4 = ((const int4*)(ei + NE))[t];
        int p;
        p = atomicAdd(&g_cnt[d4.x], 1); if (p < SLOT) g_col2[d4.x * SLOT + p] = s4.x;
        p = atomicAdd(&g_cnt[d4.y], 1); if (p < SLOT) g_col2[d4.y * SLOT + p] = s4.y;
        p = atomicAdd(&g_cnt[d4.z], 1); if (p < SLOT) g_col2[d4.z * SLOT + p] = s4.z;
        p = atomicAdd(&g_cnt[d4.w], 1); if (p < SLOT) g_col2[d4.w * SLOT + p] = s4.w;
    } else if (t < NE / 4 + NN / 4) {
        int n0 = (t - NE / 4) * 4;
#pragma unroll
        for (int k = 0; k < 4; k++) {
            int n = n0 + k;
            int p = atomicAdd(&g_cnt[n], 1);
            if (p < SLOT) g_col2[n * SLOT + p] = n;
        }
    }
}

// ---------------- FiLM (+ input proj) + tensor-core z GEMM + exact zs/zd ----------------
__global__ void k_film_z(int layer, const float* __restrict__ x,
                         const int* __restrict__ batch,
                         const float* __restrict__ Win, const float* __restrict__ bin) {
    __shared__ __half sW[H][72];
    __shared__ __half sA[32][72];
    __shared__ float  sC[32][68];
    __shared__ float  sWin[6][H];
    __shared__ float  sbin[H];
    __shared__ float  sx[32][8];
    __shared__ float  svs[H], svd[H];
    int t = threadIdx.x;
    int n0 = blockIdx.x * 32;
    // stage prepped fp16 weights via half2 copies (2048 half2 words)
    {
        const __half2* src = (const __half2*)g_Wgh[layer];
        for (int j = t; j < H * H / 2; j += 256)
            *(__half2*)&sW[j >> 5][(j & 31) * 2] = src[j];
    }
    if (t < H) { svs[t] = g_vs[layer][t]; svd[t] = g_vd[layer][t]; }
    if (layer == 0) {
        for (int i = t; i < 6 * H; i += 256) sWin[i >> 6][i & 63] = Win[i];
        if (t >= 64 && t < 128) sbin[t - 64] = bin[t - 64];
        sx[t >> 3][t & 7] = x[(n0 + (t >> 3)) * 8 + (t & 7)];
    }
    __syncthreads();

    // ---- stage 1: filmed hf (fp32), zs/zd (fp32), A tile (fp16) ----
    int nl = t >> 3, jb = (t & 7) * 8;
    int n = n0 + nl;
    int b = batch[n];
    const float* gam = ((layer == 0) ? g_gamma1 : g_gamma2) + b * H + jb;
    const float* bet = ((layer == 0) ? g_beta1  : g_beta2 ) + b * H + jb;
    float hf[8];
    if (layer == 0) {
        float xr[6];
#pragma unroll
        for (int k = 0; k < 6; k++) xr[k] = sx[nl][k];
#pragma unroll
        for (int j = 0; j < 8; j++) {
            float v = sbin[jb + j];
#pragma unroll
            for (int k = 0; k < 6; k++) v += xr[k] * sWin[k][jb + j];
            hf[j] = v;
        }
    } else {
        float4 h0 = *(const float4*)&g_hout[n * H + jb];
        float4 h1 = *(const float4*)&g_hout[n * H + jb + 4];
        hf[0] = h0.x; hf[1] = h0.y; hf[2] = h0.z; hf[3] = h0.w;
        hf[4] = h1.x; hf[5] = h1.y; hf[6] = h1.z; hf[7] = h1.w;
    }
    float4 ga = *(const float4*)&gam[0];
    float4 gb = *(const float4*)&gam[4];
    float4 ba = *(const float4*)&bet[0];
    float4 bb = *(const float4*)&bet[4];
    hf[0] = hf[0] * (1.f + ga.x) + ba.x;
    hf[1] = hf[1] * (1.f + ga.y) + ba.y;
    hf[2] = hf[2] * (1.f + ga.z) + ba.z;
    hf[3] = hf[3] * (1.f + ga.w) + ba.w;
    hf[4] = hf[4] * (1.f + gb.x) + bb.x;
    hf[5] = hf[5] * (1.f + gb.y) + bb.y;
    hf[6] = hf[6] * (1.f + gb.z) + bb.z;
    hf[7] = hf[7] * (1.f + gb.w) + bb.w;
    float ps = 0.f, pd = 0.f;
#pragma unroll
    for (int j = 0; j < 8; j++) { ps += hf[j] * svs[jb + j]; pd += hf[j] * svd[jb + j]; }
#pragma unroll
    for (int o = 4; o; o >>= 1) {
        ps += __shfl_xor_sync(0xffffffffu, ps, o);
        pd += __shfl_xor_sync(0xffffffffu, pd, o);
    }
    if ((t & 7) == 0) { g_zs[n] = ps; g_zd[n] = pd; }
    *(__half2*)&sA[nl][jb + 0] = __floats2half2_rn(hf[0], hf[1]);
    *(__half2*)&sA[nl][jb + 2] = __floats2half2_rn(hf[2], hf[3]);
    *(__half2*)&sA[nl][jb + 4] = __floats2half2_rn(hf[4], hf[5]);
    *(__half2*)&sA[nl][jb + 6] = __floats2half2_rn(hf[6], hf[7]);
    __syncthreads();

    // ---- GEMM: C[32x64] = A[32x64] x W[64x64], warp tiles M16 x N16 ----
    int w = t >> 5, l = t & 31;
    int mw = w >> 2, nw = w & 3;
    float c0[4] = {0.f, 0.f, 0.f, 0.f};
    float c1[4] = {0.f, 0.f, 0.f, 0.f};
    int arow = mw * 16 + (l & 15);
    int acol = (l >> 4) * 8;
    int brow = (l & 7) + ((l >> 3) & 1) * 8;
    int bcol = nw * 16 + (l >> 4) * 8;
#pragma unroll
    for (int kk = 0; kk < 4; kk++) {
        unsigned a0, a1, a2, a3, b0, b1, b2, b3;
        LDSM_X4(a0, a1, a2, a3, smem_u32(&sA[arow][kk * 16 + acol]));
        LDSM_X4_T(b0, b1, b2, b3, smem_u32(&sW[kk * 16 + brow][bcol]));
        MMA16816(c0, a0, a1, a2, a3, b0, b1);
        MMA16816(c1, a0, a1, a2, a3, b2, b3);
    }
    int row0 = mw * 16 + (l >> 2);
    int col0 = nw * 16 + (l & 3) * 2;
    sC[row0][col0]         = c0[0]; sC[row0][col0 + 1]     = c0[1];
    sC[row0 + 8][col0]     = c0[2]; sC[row0 + 8][col0 + 1] = c0[3];
    sC[row0][col0 + 8]     = c1[0]; sC[row0][col0 + 9]     = c1[1];
    sC[row0 + 8][col0 + 8] = c1[2]; sC[row0 + 8][col0 + 9] = c1[3];
    __syncthreads();

    // ---- epilogue: z -> fp16 global (coalesced) ----
    float4 z0 = *(float4*)&sC[nl][jb];
    float4 z1 = *(float4*)&sC[nl][jb + 4];
    __align__(16) __half ho[8];
    ho[0] = __float2half(z0.x); ho[1] = __float2half(z0.y);
    ho[2] = __float2half(z0.z); ho[3] = __float2half(z0.w);
    ho[4] = __float2half(z1.x); ho[5] = __float2half(z1.y);
    ho[6] = __float2half(z1.z); ho[7] = __float2half(z1.w);
    *(float4*)&g_zh[n * H + jb] = *(float4*)ho;
}

// ---------------- fused GAT: warp per 2 nodes; warp-coop softmax -> smem -> gather --------
__global__ void k_gat_ws(int layer, const float* __restrict__ bg) {
    __shared__ float swgt[8][2][SLOT];
    __shared__ int   soff[8][2][SLOT];
    int gw = (blockIdx.x * blockDim.x + threadIdx.x) >> 5;
    int wb = threadIdx.x >> 5;
    int lane = threadIdx.x & 31;
    int nl = lane >> 4, hl = lane & 15;
    int n = gw * 2 + nl;
    if (n >= NN) return;               // NN even: whole warp exits together
    int cnt = min(g_cnt[n], SLOT);
    int cmax = max(cnt, __shfl_xor_sync(0xffffffffu, cnt, 16));  // warp-uniform
    int rounds = (cmax + 15) >> 4;
    const int* __restrict__ cols = g_col2 + n * SLOT;
    float zdd = g_zd[n];
    float ev0 = -1e30f, ev1 = -1e30f, ev2 = -1e30f, ev3 = -1e30f;
#define LOGIT(r, ev)                                            \
    if (r < rounds) {                                           \
        int i = r * 16 + hl;                                    \
        int of = 0;                                             \
        if (i < cnt) {                                          \
            int s = cols[i];                                    \
            float tv = g_zs[s] + zdd;                           \
            ev = fmaxf(tv, 0.2f * tv);                          \
            of = s << 6;                                        \
        }                                                       \
        soff[wb][nl][i] = of;                                   \
    }
    LOGIT(0, ev0) LOGIT(1, ev1) LOGIT(2, ev2) LOGIT(3, ev3)
#undef LOGIT
    float m = fmaxf(fmaxf(ev0, ev1), fmaxf(ev2, ev3));
#pragma unroll
    for (int o = 8; o; o >>= 1) m = fmaxf(m, __shfl_xor_sync(0xffffffffu, m, o));
    float w0 = __expf(ev0 - m), w1 = __expf(ev1 - m);
    float w2 = __expf(ev2 - m), w3 = __expf(ev3 - m);
    float sum = (w0 + w1) + (w2 + w3);
#pragma unroll
    for (int o = 8; o; o >>= 1) sum += __shfl_xor_sync(0xffffffffu, sum, o);
    float invs = 1.f / (sum + 1e-16f);
    if (0 < rounds) swgt[wb][nl][hl]      = w0 * invs;
    if (1 < rounds) swgt[wb][nl][16 + hl] = w1 * invs;
    if (2 < rounds) swgt[wb][nl][32 + hl] = w2 * invs;
    if (3 < rounds) swgt[wb][nl][48 + hl] = w3 * invs;
    __syncwarp();

    // phase 2: weighted gather
    int g2 = (lane >> 3) & 1, ql = lane & 7;
    int trips = (cmax + 1) >> 1;
    const __half* __restrict__ zbase = g_zh + 8 * ql;
    float acc[8] = {0.f, 0.f, 0.f, 0.f, 0.f, 0.f, 0.f, 0.f};
#pragma unroll 2
    for (int j = 0; j < trips; j++) {
        int i = 2 * j + g2;
        float wgt = swgt[wb][nl][i];
        int   of  = soff[wb][nl][i];
        float4 raw = *(const float4*)(zbase + of);
        const __half2* hp = (const __half2*)&raw;
        float2 f0 = __half22float2(hp[0]);
        float2 f1 = __half22float2(hp[1]);
        float2 f2 = __half22float2(hp[2]);
        float2 f3 = __half22float2(hp[3]);
        acc[0] += wgt * f0.x; acc[1] += wgt * f0.y;
        acc[2] += wgt * f1.x; acc[3] += wgt * f1.y;
        acc[4] += wgt * f2.x; acc[5] += wgt * f2.y;
        acc[6] += wgt * f3.x; acc[7] += wgt * f3.y;
    }
#pragma unroll
    for (int k = 0; k < 8; k++) acc[k] += __shfl_xor_sync(0xffffffffu, acc[k], 8);
    float* out = (layer == 0) ? g_hout : g_h2;
    int fo = 8 * ql + 4 * g2;
    float4 bv = *(const float4*)&bg[fo];
    int ai = 4 * g2;
    float4 oo = { fmaxf(acc[ai + 0] + bv.x, 0.f),
                  fmaxf(acc[ai + 1] + bv.y, 0.f),
                  fmaxf(acc[ai + 2] + bv.z, 0.f),
                  fmaxf(acc[ai + 3] + bv.w, 0.f) };
    *(float4*)&out[n * H + fo] = oo;
}

// ---------------- classifier (tensor-core) + flag head ----------------
__global__ void k_cls(const float* __restrict__ x,
                      const float* __restrict__ bc1,
                      const float* __restrict__ Wc2, const float* __restrict__ bc2,
                      const float* __restrict__ Wh1, const float* __restrict__ bh1,
                      const float* __restrict__ Wh2, const float* __restrict__ bh2,
                      float* __restrict__ out) {
    __shared__ __half sW[H][72];
    __shared__ __half sA[32][72];
    __shared__ float  sC[32][68];
    __shared__ float  sbc1[H];
    __shared__ float  sW2[H * 4];
    __shared__ float  sWh1[16], sbh1[8], sWh2[32], sbh2[4], sbc2[4];
    int t = threadIdx.x;
    int n0 = blockIdx.x * 32;
    {
        const __half2* src = (const __half2*)g_Wc1h;
        for (int j = t; j < H * H / 2; j += 256)
            *(__half2*)&sW[j >> 5][(j & 31) * 2] = src[j];
    }
    if (t < H) sbc1[t] = bc1[t];
    if (t < 256) sW2[t] = Wc2[t];
    if (t < 16) sWh1[t] = Wh1[t];
    if (t < 8)  sbh1[t] = bh1[t];
    if (t < 32) sWh2[t] = Wh2[t];
    if (t < 4)  { sbh2[t] = bh2[t]; sbc2[t] = bc2[t]; }
    // stage h2 rows as fp16
    int nl = t >> 3, jb = (t & 7) * 8;
    int n = n0 + nl;
    {
        float4 h0 = *(const float4*)&g_h2[n * H + jb];
        float4 h1 = *(const float4*)&g_h2[n * H + jb + 4];
        *(__half2*)&sA[nl][jb + 0] = __floats2half2_rn(h0.x, h0.y);
        *(__half2*)&sA[nl][jb + 2] = __floats2half2_rn(h0.z, h0.w);
        *(__half2*)&sA[nl][jb + 4] = __floats2half2_rn(h1.x, h1.y);
        *(__half2*)&sA[nl][jb + 6] = __floats2half2_rn(h1.z, h1.w);
    }
    __syncthreads();

    // ---- GEMM: C[32x64] = A x Wc1 ----
    int w = t >> 5, l = t & 31;
    int mw = w >> 2, nw = w & 3;
    float c0[4] = {0.f, 0.f, 0.f, 0.f};
    float c1[4] = {0.f, 0.f, 0.f, 0.f};
    int arow = mw * 16 + (l & 15);
    int acol = (l >> 4) * 8;
    int brow = (l & 7) + ((l >> 3) & 1) * 8;
    int bcol = nw * 16 + (l >> 4) * 8;
#pragma unroll
    for (int kk = 0; kk < 4; kk++) {
        unsigned a0, a1, a2, a3, b0, b1, b2, b3;
        LDSM_X4(a0, a1, a2, a3, smem_u32(&sA[arow][kk * 16 + acol]));
        LDSM_X4_T(b0, b1, b2, b3, smem_u32(&sW[kk * 16 + brow][bcol]));
        MMA16816(c0, a0, a1, a2, a3, b0, b1);
        MMA16816(c1, a0, a1, a2, a3, b2, b3);
    }
    int row0 = mw * 16 + (l >> 2);
    int col0 = nw * 16 + (l & 3) * 2;
    sC[row0][col0]         = c0[0]; sC[row0][col0 + 1]     = c0[1];
    sC[row0 + 8][col0]     = c0[2]; sC[row0 + 8][col0 + 1] = c0[3];
    sC[row0][col0 + 8]     = c1[0]; sC[row0][col0 + 9]     = c1[1];
    sC[row0 + 8][col0 + 8] = c1[2]; sC[row0 + 8][col0 + 9] = c1[3];
    __syncthreads();

    // ---- final: relu(C+bc1) @ Wc2 + bc2 + 0.03*flag ----
    if (t < 128) {
        int onl = t >> 2, oj = t & 3;
        int on = n0 + onl;
        float cacc = sbc2[oj];
#pragma unroll
        for (int k = 0; k < H; k++)
            cacc += fmaxf(sC[onl][k] + sbc1[k], 0.f) * sW2[k * 4 + oj];
        float f0 = x[on * 8 + 6], f1 = x[on * 8 + 7];
        float facc = sbh2[oj];
#pragma unroll
        for (int m = 0; m < 8; m++) {
            float u = fmaxf(f0 * sWh1[m] + f1 * sWh1[8 + m] + sbh1[m], 0.f);
            facc += u * sWh2[m * 4 + oj];
        }
        out[on * 4 + oj] = cacc + 0.03f * facc;
    }
}

// ---------------- launch ----------------
extern "C" void kernel_launch(void* const* d_in, const int* in_sizes, int n_in,
                              void* d_out, int out_size) {
    const float* x       = (const float*)d_in[0];
    const int*   ei      = (const int*)  d_in[1];
    const int*   batch   = (const int*)  d_in[2];
    const float* climber = (const float*)d_in[3];
    const float* W_in    = (const float*)d_in[4];
    const float* b_in    = (const float*)d_in[5];
    const float* ln_g    = (const float*)d_in[6];
    const float* ln_b    = (const float*)d_in[7];
    const float* W_c     = (const float*)d_in[8];
    const float* b_c     = (const float*)d_in[9];
    const float* Wf1     = (const float*)d_in[10];
    const float* bf1     = (const float*)d_in[11];
    const float* Wf2     = (const float*)d_in[12];
    const float* bf2     = (const float*)d_in[13];
    const float* Wg1     = (const float*)d_in[14];
    const float* as1     = (const float*)d_in[15];
    const float* ad1     = (const float*)d_in[16];
    const float* bg1     = (const float*)d_in[17];
    const float* Wg2     = (const float*)d_in[18];
    const float* as2     = (const float*)d_in[19];
    const float* ad2     = (const float*)d_in[20];
    const float* bg2     = (const float*)d_in[21];
    const float* Wc1     = (const float*)d_in[22];
    const float* bc1     = (const float*)d_in[23];
    const float* Wc2     = (const float*)d_in[24];
    const float* bc2     = (const float*)d_in[25];
    const float* Wh1     = (const float*)d_in[26];
    const float* bh1     = (const float*)d_in[27];
    const float* Wh2     = (const float*)d_in[28];
    const float* bh2     = (const float*)d_in[29];
    float* out = (float*)d_out;

    k_climber_zero<<<NG + NZB + 5, 128>>>(climber, ln_g, ln_b, W_c, b_c,
                                          Wf1, bf1, Wf2, bf2,
                                          Wg1, as1, ad1, Wg2, as2, ad2, Wc1);
    k_fill<<<(NE / 4 + NN / 4 + 255) / 256, 256>>>(ei);

    k_film_z<<<NN / 32, 256>>>(0, x, batch, W_in, b_in);
    k_gat_ws<<<NN / 16, 256>>>(0, bg1);

    k_film_z<<<NN / 32, 256>>>(1, x, batch, W_in, b_in);
    k_gat_ws<<<NN / 16, 256>>>(1, bg2);

    k_cls<<<NN / 32, 256>>>(x, bc1, Wc2, bc2, Wh1, bh1, Wh2, bh2, out);
}

// round 14
// speedup vs baseline: 1.8580x; 1.0544x over previous
#include <cuda_runtime.h>
#include <cuda_fp16.h>

#define NN 100000
#define NE 1200000
#define NG 1000
#define H  64
#define TOT_E (NE + NN)
#define SLOT 64
#define NZB  ((NN + 127) / 128)

// ---------------- scratch (no allocations allowed) ----------------
__device__ __half g_zh[NN * H];    // z in fp16 (values only; logits stay fp32)
__device__ float  g_hout[NN * H];  // gat1 output / film2 input (fp32: feeds layer-2 logits)
__device__ __half g_h2h[NN * H];   // gat2 output / cls input (fp16: cls rounds anyway)
__device__ float g_zs[NN];
__device__ float g_zd[NN];
__device__ float g_vs[2][H], g_vd[2][H];  // Wg @ a_src, Wg @ a_dst (fp32, exact logits)
__device__ __half g_Wgh[2][H * H];        // fp16 Wg1, Wg2 (prepped once)
__device__ __half g_Wc1h[H * H];          // fp16 Wc1
__device__ int   g_cnt[NN];
__device__ int   g_col2[NN * SLOT];
__device__ float g_gamma1[NG * H], g_beta1[NG * H];
__device__ float g_gamma2[NG * H], g_beta2[NG * H];

__device__ __forceinline__ unsigned smem_u32(const void* p) {
    return (unsigned)__cvta_generic_to_shared(p);
}

#define LDSM_X4(r0, r1, r2, r3, addr)                                          \
    asm volatile("ldmatrix.sync.aligned.m8n8.x4.shared.b16 {%0,%1,%2,%3}, [%4];" \
                 : "=r"(r0), "=r"(r1), "=r"(r2), "=r"(r3) : "r"(addr))
#define LDSM_X4_T(r0, r1, r2, r3, addr)                                        \
    asm volatile("ldmatrix.sync.aligned.m8n8.x4.trans.shared.b16 {%0,%1,%2,%3}, [%4];" \
                 : "=r"(r0), "=r"(r1), "=r"(r2), "=r"(r3) : "r"(addr))
#define MMA16816(c, a0, a1, a2, a3, b0, b1)                                    \
    asm volatile("mma.sync.aligned.m16n8k16.row.col.f32.f16.f16.f32 "          \
                 "{%0,%1,%2,%3}, {%4,%5,%6,%7}, {%8,%9}, {%0,%1,%2,%3};"       \
                 : "+f"(c[0]), "+f"(c[1]), "+f"(c[2]), "+f"(c[3])              \
                 : "r"(a0), "r"(a1), "r"(a2), "r"(a3), "r"(b0), "r"(b1))

// ---------------- prep: climber MLP + FiLM + cnt zero + v vectors + fp16 weights --------
__global__ void k_climber_zero(const float* __restrict__ climber,
                               const float* __restrict__ ln_g, const float* __restrict__ ln_b,
                               const float* __restrict__ W_c,  const float* __restrict__ b_c,
                               const float* __restrict__ Wf1,  const float* __restrict__ bf1,
                               const float* __restrict__ Wf2,  const float* __restrict__ bf2,
                               const float* __restrict__ Wg1,  const float* __restrict__ as1,
                               const float* __restrict__ ad1,
                               const float* __restrict__ Wg2,  const float* __restrict__ as2,
                               const float* __restrict__ ad2,
                               const float* __restrict__ Wc1) {
    int t = threadIdx.x;
    if (blockIdx.x >= NG + NZB + 2) {
        // fp16 weight conversion: one block per matrix
        int which = blockIdx.x - (NG + NZB + 2);   // 0:Wg1 1:Wg2 2:Wc1
        const float* W = (which == 0) ? Wg1 : (which == 1) ? Wg2 : Wc1;
        __half* D = (which == 0) ? g_Wgh[0] : (which == 1) ? g_Wgh[1] : g_Wc1h;
        for (int i = t; i < H * H; i += 128) D[i] = __float2half(W[i]);
        return;
    }
    if (blockIdx.x >= NG + NZB) {
        // v = Wg @ a : which in {0:Wg1*as1, 1:Wg1*ad1, 2:Wg2*as2, 3:Wg2*ad2}
        int which = (blockIdx.x - (NG + NZB)) * 2 + (t >> 6);
        int k = t & 63;
        const float* W = (which < 2) ? Wg1 : Wg2;
        const float* a = (which & 1) ? ((which < 2) ? ad1 : ad2)
                                     : ((which < 2) ? as1 : as2);
        float v = 0.f;
#pragma unroll 8
        for (int j = 0; j < H; j++) v += W[k * H + j] * a[j];
        if (which & 1) g_vd[which >> 1][k] = v;
        else           g_vs[which >> 1][k] = v;
        return;
    }
    if (blockIdx.x >= NG) {
        int i = (blockIdx.x - NG) * 128 + t;
        if (i < NN) g_cnt[i] = 0;
        return;
    }
    __shared__ float cv[6], cn[6], c_sh[H];
    int g = blockIdx.x;
    if (t < 6) cv[t] = climber[g * 6 + t];
    __syncthreads();
    float mu = (cv[0] + cv[1] + cv[2] + cv[3] + cv[4] + cv[5]) * (1.0f / 6.0f);
    float var = 0.f;
#pragma unroll
    for (int k = 0; k < 6; k++) { float d = cv[k] - mu; var += d * d; }
    var *= (1.0f / 6.0f);
    float rstd = rsqrtf(var + 1e-5f);
    if (t < 6) cn[t] = (cv[t] - mu) * rstd * ln_g[t] + ln_b[t];
    __syncthreads();
    if (t < H) {
        float a = b_c[t];
#pragma unroll
        for (int k = 0; k < 6; k++) a += cn[k] * W_c[k * H + t];
        c_sh[t] = fmaxf(a, 0.f);
    }
    __syncthreads();
    float a1 = bf1[t], a2 = bf2[t];
    for (int k = 0; k < H; k++) {
        float cc = c_sh[k];
        a1 += cc * Wf1[k * 128 + t];
        a2 += cc * Wf2[k * 128 + t];
    }
    if (t < H) { g_gamma1[g * H + t] = a1; g_gamma2[g * H + t] = a2; }
    else       { g_beta1[g * H + t - H] = a1; g_beta2[g * H + t - H] = a2; }
}

// ---------------- padded-adjacency fill, 4 edges per thread (MLP=4) ----------------
__global__ void k_fill(const int* __restrict__ ei) {
    int t = blockIdx.x * blockDim.x + threadIdx.x;
    if (t < NE / 4) {
        int4 s4 = ((const int4*)ei)[t];
        int4 d4 = ((const int4*)(ei + NE))[t];
        int p;
        p = atomicAdd(&g_cnt[d4.x], 1); if (p < SLOT) g_col2[d4.x * SLOT + p] = s4.x;
        p = atomicAdd(&g_cnt[d4.y], 1); if (p < SLOT) g_col2[d4.y * SLOT + p] = s4.y;
        p = atomicAdd(&g_cnt[d4.z], 1); if (p < SLOT) g_col2[d4.z * SLOT + p] = s4.z;
        p = atomicAdd(&g_cnt[d4.w], 1); if (p < SLOT) g_col2[d4.w * SLOT + p] = s4.w;
    } else if (t < NE / 4 + NN / 4) {
        int n0 = (t - NE / 4) * 4;
#pragma unroll
        for (int k = 0; k < 4; k++) {
            int n = n0 + k;
            int p = atomicAdd(&g_cnt[n], 1);
            if (p < SLOT) g_col2[n * SLOT + p] = n;
        }
    }
}

// ---------------- FiLM (+ input proj) + tensor-core z GEMM + exact zs/zd ----------------
__global__ void k_film_z(int layer, const float* __restrict__ x,
                         const int* __restrict__ batch,
                         const float* __restrict__ Win, const float* __restrict__ bin) {
    __shared__ __half sW[H][72];
    __shared__ __half sA[32][72];
    __shared__ float  sC[32][68];
    __shared__ float  sWin[6][H];
    __shared__ float  sbin[H];
    __shared__ float  sx[32][8];
    __shared__ float  svs[H], svd[H];
    int t = threadIdx.x;
    int n0 = blockIdx.x * 32;
    // stage prepped fp16 weights via half2 copies (2048 half2 words)
    {
        const __half2* src = (const __half2*)g_Wgh[layer];
        for (int j = t; j < H * H / 2; j += 256)
            *(__half2*)&sW[j >> 5][(j & 31) * 2] = src[j];
    }
    if (t < H) { svs[t] = g_vs[layer][t]; svd[t] = g_vd[layer][t]; }
    if (layer == 0) {
        for (int i = t; i < 6 * H; i += 256) sWin[i >> 6][i & 63] = Win[i];
        if (t >= 64 && t < 128) sbin[t - 64] = bin[t - 64];
        sx[t >> 3][t & 7] = x[(n0 + (t >> 3)) * 8 + (t & 7)];
    }
    __syncthreads();

    // ---- stage 1: filmed hf (fp32), zs/zd (fp32), A tile (fp16) ----
    int nl = t >> 3, jb = (t & 7) * 8;
    int n = n0 + nl;
    int b = batch[n];
    const float* gam = ((layer == 0) ? g_gamma1 : g_gamma2) + b * H + jb;
    const float* bet = ((layer == 0) ? g_beta1  : g_beta2 ) + b * H + jb;
    float hf[8];
    if (layer == 0) {
        float xr[6];
#pragma unroll
        for (int k = 0; k < 6; k++) xr[k] = sx[nl][k];
#pragma unroll
        for (int j = 0; j < 8; j++) {
            float v = sbin[jb + j];
#pragma unroll
            for (int k = 0; k < 6; k++) v += xr[k] * sWin[k][jb + j];
            hf[j] = v;
        }
    } else {
        float4 h0 = *(const float4*)&g_hout[n * H + jb];
        float4 h1 = *(const float4*)&g_hout[n * H + jb + 4];
        hf[0] = h0.x; hf[1] = h0.y; hf[2] = h0.z; hf[3] = h0.w;
        hf[4] = h1.x; hf[5] = h1.y; hf[6] = h1.z; hf[7] = h1.w;
    }
    float4 ga = *(const float4*)&gam[0];
    float4 gb = *(const float4*)&gam[4];
    float4 ba = *(const float4*)&bet[0];
    float4 bb = *(const float4*)&bet[4];
    hf[0] = hf[0] * (1.f + ga.x) + ba.x;
    hf[1] = hf[1] * (1.f + ga.y) + ba.y;
    hf[2] = hf[2] * (1.f + ga.z) + ba.z;
    hf[3] = hf[3] * (1.f + ga.w) + ba.w;
    hf[4] = hf[4] * (1.f + gb.x) + bb.x;
    hf[5] = hf[5] * (1.f + gb.y) + bb.y;
    hf[6] = hf[6] * (1.f + gb.z) + bb.z;
    hf[7] = hf[7] * (1.f + gb.w) + bb.w;
    float ps = 0.f, pd = 0.f;
#pragma unroll
    for (int j = 0; j < 8; j++) { ps += hf[j] * svs[jb + j]; pd += hf[j] * svd[jb + j]; }
#pragma unroll
    for (int o = 4; o; o >>= 1) {
        ps += __shfl_xor_sync(0xffffffffu, ps, o);
        pd += __shfl_xor_sync(0xffffffffu, pd, o);
    }
    if ((t & 7) == 0) { g_zs[n] = ps; g_zd[n] = pd; }
    *(__half2*)&sA[nl][jb + 0] = __floats2half2_rn(hf[0], hf[1]);
    *(__half2*)&sA[nl][jb + 2] = __floats2half2_rn(hf[2], hf[3]);
    *(__half2*)&sA[nl][jb + 4] = __floats2half2_rn(hf[4], hf[5]);
    *(__half2*)&sA[nl][jb + 6] = __floats2half2_rn(hf[6], hf[7]);
    __syncthreads();

    // ---- GEMM: C[32x64] = A[32x64] x W[64x64], warp tiles M16 x N16 ----
    int w = t >> 5, l = t & 31;
    int mw = w >> 2, nw = w & 3;
    float c0[4] = {0.f, 0.f, 0.f, 0.f};
    float c1[4] = {0.f, 0.f, 0.f, 0.f};
    int arow = mw * 16 + (l & 15);
    int acol = (l >> 4) * 8;
    int brow = (l & 7) + ((l >> 3) & 1) * 8;
    int bcol = nw * 16 + (l >> 4) * 8;
#pragma unroll
    for (int kk = 0; kk < 4; kk++) {
        unsigned a0, a1, a2, a3, b0, b1, b2, b3;
        LDSM_X4(a0, a1, a2, a3, smem_u32(&sA[arow][kk * 16 + acol]));
        LDSM_X4_T(b0, b1, b2, b3, smem_u32(&sW[kk * 16 + brow][bcol]));
        MMA16816(c0, a0, a1, a2, a3, b0, b1);
        MMA16816(c1, a0, a1, a2, a3, b2, b3);
    }
    int row0 = mw * 16 + (l >> 2);
    int col0 = nw * 16 + (l & 3) * 2;
    sC[row0][col0]         = c0[0]; sC[row0][col0 + 1]     = c0[1];
    sC[row0 + 8][col0]     = c0[2]; sC[row0 + 8][col0 + 1] = c0[3];
    sC[row0][col0 + 8]     = c1[0]; sC[row0][col0 + 9]     = c1[1];
    sC[row0 + 8][col0 + 8] = c1[2]; sC[row0 + 8][col0 + 9] = c1[3];
    __syncthreads();

    // ---- epilogue: z -> fp16 global (coalesced) ----
    float4 z0 = *(float4*)&sC[nl][jb];
    float4 z1 = *(float4*)&sC[nl][jb + 4];
    __align__(16) __half ho[8];
    ho[0] = __float2half(z0.x); ho[1] = __float2half(z0.y);
    ho[2] = __float2half(z0.z); ho[3] = __float2half(z0.w);
    ho[4] = __float2half(z1.x); ho[5] = __float2half(z1.y);
    ho[6] = __float2half(z1.z); ho[7] = __float2half(z1.w);
    *(float4*)&g_zh[n * H + jb] = *(float4*)ho;
}

// ---------------- fused GAT: warp per 2 nodes; warp-coop softmax -> smem -> gather --------
// (wgt, off) packed in float2 smem -> single LDS.64 per edge in the gather loop.
__global__ void k_gat_ws(int layer, const float* __restrict__ bg) {
    __shared__ float2 swp[8][2][SLOT];   // .x = normalized weight, .y = offset bits
    int gw = (blockIdx.x * blockDim.x + threadIdx.x) >> 5;
    int wb = threadIdx.x >> 5;
    int lane = threadIdx.x & 31;
    int nl = lane >> 4, hl = lane & 15;
    int n = gw * 2 + nl;
    if (n >= NN) return;               // NN even: whole warp exits together
    int cnt = min(g_cnt[n], SLOT);
    int cmax = max(cnt, __shfl_xor_sync(0xffffffffu, cnt, 16));  // warp-uniform
    int rounds = (cmax + 15) >> 4;
    const int* __restrict__ cols = g_col2 + n * SLOT;
    float zdd = g_zd[n];
    float ev0 = -1e30f, ev1 = -1e30f, ev2 = -1e30f, ev3 = -1e30f;
#define LOGIT(r, ev)                                            \
    if (r < rounds) {                                           \
        int i = r * 16 + hl;                                    \
        int of = 0;                                             \
        if (i < cnt) {                                          \
            int s = cols[i];                                    \
            float tv = g_zs[s] + zdd;                           \
            ev = fmaxf(tv, 0.2f * tv);                          \
            of = s << 6;                                        \
        }                                                       \
        swp[wb][nl][i].y = __int_as_float(of);                  \
    }
    LOGIT(0, ev0) LOGIT(1, ev1) LOGIT(2, ev2) LOGIT(3, ev3)
#undef LOGIT
    float m = fmaxf(fmaxf(ev0, ev1), fmaxf(ev2, ev3));
#pragma unroll
    for (int o = 8; o; o >>= 1) m = fmaxf(m, __shfl_xor_sync(0xffffffffu, m, o));
    float w0 = __expf(ev0 - m), w1 = __expf(ev1 - m);
    float w2 = __expf(ev2 - m), w3 = __expf(ev3 - m);
    float sum = (w0 + w1) + (w2 + w3);
#pragma unroll
    for (int o = 8; o; o >>= 1) sum += __shfl_xor_sync(0xffffffffu, sum, o);
    float invs = 1.f / (sum + 1e-16f);
    if (0 < rounds) swp[wb][nl][hl].x      = w0 * invs;
    if (1 < rounds) swp[wb][nl][16 + hl].x = w1 * invs;
    if (2 < rounds) swp[wb][nl][32 + hl].x = w2 * invs;
    if (3 < rounds) swp[wb][nl][48 + hl].x = w3 * invs;
    __syncwarp();

    // phase 2: weighted gather (single LDS.64 per edge per lane)
    int g2 = (lane >> 3) & 1, ql = lane & 7;
    int trips = (cmax + 1) >> 1;
    const __half* __restrict__ zbase = g_zh + 8 * ql;
    float acc[8] = {0.f, 0.f, 0.f, 0.f, 0.f, 0.f, 0.f, 0.f};
#pragma unroll 4
    for (int j = 0; j < trips; j++) {
        int i = 2 * j + g2;
        float2 wo = swp[wb][nl][i];
        float wgt = wo.x;
        int   of  = __float_as_int(wo.y);
        float4 raw = *(const float4*)(zbase + of);
        const __half2* hp = (const __half2*)&raw;
        float2 f0 = __half22float2(hp[0]);
        float2 f1 = __half22float2(hp[1]);
        float2 f2 = __half22float2(hp[2]);
        float2 f3 = __half22float2(hp[3]);
        acc[0] += wgt * f0.x; acc[1] += wgt * f0.y;
        acc[2] += wgt * f1.x; acc[3] += wgt * f1.y;
        acc[4] += wgt * f2.x; acc[5] += wgt * f2.y;
        acc[6] += wgt * f3.x; acc[7] += wgt * f3.y;
    }
#pragma unroll
    for (int k = 0; k < 8; k++) acc[k] += __shfl_xor_sync(0xffffffffu, acc[k], 8);
    int fo = 8 * ql + 4 * g2;
    float4 bv = *(const float4*)&bg[fo];
    int ai = 4 * g2;
    float o0 = fmaxf(acc[ai + 0] + bv.x, 0.f);
    float o1 = fmaxf(acc[ai + 1] + bv.y, 0.f);
    float o2 = fmaxf(acc[ai + 2] + bv.z, 0.f);
    float o3 = fmaxf(acc[ai + 3] + bv.w, 0.f);
    if (layer == 0) {
        float4 oo = {o0, o1, o2, o3};
        *(float4*)&g_hout[n * H + fo] = oo;
    } else {
        // fp16 store — identical rounding to what k_cls applied previously
        __align__(8) __half2 ho[2];
        ho[0] = __floats2half2_rn(o0, o1);
        ho[1] = __floats2half2_rn(o2, o3);
        *(uint2*)&g_h2h[n * H + fo] = *(uint2*)ho;
    }
}

// ---------------- classifier (tensor-core) + flag head ----------------
__global__ void k_cls(const float* __restrict__ x,
                      const float* __restrict__ bc1,
                      const float* __restrict__ Wc2, const float* __restrict__ bc2,
                      const float* __restrict__ Wh1, const float* __restrict__ bh1,
                      const float* __restrict__ Wh2, const float* __restrict__ bh2,
                      float* __restrict__ out) {
    __shared__ __half sW[H][72];
    __shared__ __half sA[32][72];
    __shared__ float  sC[32][68];
    __shared__ float  sbc1[H];
    __shared__ float  sW2[H * 4];
    __shared__ float  sWh1[16], sbh1[8], sWh2[32], sbh2[4], sbc2[4];
    int t = threadIdx.x;
    int n0 = blockIdx.x * 32;
    {
        const __half2* src = (const __half2*)g_Wc1h;
        for (int j = t; j < H * H / 2; j += 256)
            *(__half2*)&sW[j >> 5][(j & 31) * 2] = src[j];
    }
    if (t < H) sbc1[t] = bc1[t];
    if (t < 256) sW2[t] = Wc2[t];
    if (t < 16) sWh1[t] = Wh1[t];
    if (t < 8)  sbh1[t] = bh1[t];
    if (t < 32) sWh2[t] = Wh2[t];
    if (t < 4)  { sbh2[t] = bh2[t]; sbc2[t] = bc2[t]; }
    // stage h2 rows (already fp16) — pure 16B copy
    int nl = t >> 3, jb = (t & 7) * 8;
    int n = n0 + nl;
    *(float4*)&sA[nl][jb] = *(const float4*)&g_h2h[n * H + jb];
    __syncthreads();

    // ---- GEMM: C[32x64] = A x Wc1 ----
    int w = t >> 5, l = t & 31;
    int mw = w >> 2, nw = w & 3;
    float c0[4] = {0.f, 0.f, 0.f, 0.f};
    float c1[4] = {0.f, 0.f, 0.f, 0.f};
    int arow = mw * 16 + (l & 15);
    int acol = (l >> 4) * 8;
    int brow = (l & 7) + ((l >> 3) & 1) * 8;
    int bcol = nw * 16 + (l >> 4) * 8;
#pragma unroll
    for (int kk = 0; kk < 4; kk++) {
        unsigned a0, a1, a2, a3, b0, b1, b2, b3;
        LDSM_X4(a0, a1, a2, a3, smem_u32(&sA[arow][kk * 16 + acol]));
        LDSM_X4_T(b0, b1, b2, b3, smem_u32(&sW[kk * 16 + brow][bcol]));
        MMA16816(c0, a0, a1, a2, a3, b0, b1);
        MMA16816(c1, a0, a1, a2, a3, b2, b3);
    }
    int row0 = mw * 16 + (l >> 2);
    int col0 = nw * 16 + (l & 3) * 2;
    sC[row0][col0]         = c0[0]; sC[row0][col0 + 1]     = c0[1];
    sC[row0 + 8][col0]     = c0[2]; sC[row0 + 8][col0 + 1] = c0[3];
    sC[row0][col0 + 8]     = c1[0]; sC[row0][col0 + 9]     = c1[1];
    sC[row0 + 8][col0 + 8] = c1[2]; sC[row0 + 8][col0 + 9] = c1[3];
    __syncthreads();

    // ---- final: relu(C+bc1) @ Wc2 + bc2 + 0.03*flag ----
    if (t < 128) {
        int onl = t >> 2, oj = t & 3;
        int on = n0 + onl;
        float cacc = sbc2[oj];
#pragma unroll
        for (int k = 0; k < H; k++)
            cacc += fmaxf(sC[onl][k] + sbc1[k], 0.f) * sW2[k * 4 + oj];
        float f0 = x[on * 8 + 6], f1 = x[on * 8 + 7];
        float facc = sbh2[oj];
#pragma unroll
        for (int m = 0; m < 8; m++) {
            float u = fmaxf(f0 * sWh1[m] + f1 * sWh1[8 + m] + sbh1[m], 0.f);
            facc += u * sWh2[m * 4 + oj];
        }
        out[on * 4 + oj] = cacc + 0.03f * facc;
    }
}

// ---------------- launch ----------------
extern "C" void kernel_launch(void* const* d_in, const int* in_sizes, int n_in,
                              void* d_out, int out_size) {
    const float* x       = (const float*)d_in[0];
    const int*   ei      = (const int*)  d_in[1];
    const int*   batch   = (const int*)  d_in[2];
    const float* climber = (const float*)d_in[3];
    const float* W_in    = (const float*)d_in[4];
    const float* b_in    = (const float*)d_in[5];
    const float* ln_g    = (const float*)d_in[6];
    const float* ln_b    = (const float*)d_in[7];
    const float* W_c     = (const float*)d_in[8];
    const float* b_c     = (const float*)d_in[9];
    const float* Wf1     = (const float*)d_in[10];
    const float* bf1     = (const float*)d_in[11];
    const float* Wf2     = (const float*)d_in[12];
    const float* bf2     = (const float*)d_in[13];
    const float* Wg1     = (const float*)d_in[14];
    const float* as1     = (const float*)d_in[15];
    const float* ad1     = (const float*)d_in[16];
    const float* bg1     = (const float*)d_in[17];
    const float* Wg2     = (const float*)d_in[18];
    const float* as2     = (const float*)d_in[19];
    const float* ad2     = (const float*)d_in[20];
    const float* bg2     = (const float*)d_in[21];
    const float* Wc1     = (const float*)d_in[22];
    const float* bc1     = (const float*)d_in[23];
    const float* Wc2     = (const float*)d_in[24];
    const float* bc2     = (const float*)d_in[25];
    const float* Wh1     = (const float*)d_in[26];
    const float* bh1     = (const float*)d_in[27];
    const float* Wh2     = (const float*)d_in[28];
    const float* bh2     = (const float*)d_in[29];
    float* out = (float*)d_out;

    k_climber_zero<<<NG + NZB + 5, 128>>>(climber, ln_g, ln_b, W_c, b_c,
                                          Wf1, bf1, Wf2, bf2,
                                          Wg1, as1, ad1, Wg2, as2, ad2, Wc1);
    k_fill<<<(NE / 4 + NN / 4 + 255) / 256, 256>>>(ei);

    k_film_z<<<NN / 32, 256>>>(0, x, batch, W_in, b_in);
    k_gat_ws<<<NN / 16, 256>>>(0, bg1);

    k_film_z<<<NN / 32, 256>>>(1, x, batch, W_in, b_in);
    k_gat_ws<<<NN / 16, 256>>>(1, bg2);

    k_cls<<<NN / 32, 256>>>(x, bc1, Wc2, bc2, Wh1, bh1, Wh2, bh2, out);
}

// round 15
// speedup vs baseline: 1.8725x; 1.0078x over previous
#include <cuda_runtime.h>
#include <cuda_fp16.h>

#define NN 100000
#define NE 1200000
#define NG 1000
#define H  64
#define TOT_E (NE + NN)
#define SLOT 64
#define NZB  ((NN + 127) / 128)

// ---------------- scratch (no allocations allowed) ----------------
__device__ __half g_zh[NN * H];    // z in fp16 (values only; logits stay fp32)
__device__ float  g_hout[NN * H];  // gat1 output / film2 input (fp32: feeds layer-2 logits)
__device__ __half g_h2h[NN * H];   // gat2 output / cls input (fp16: cls rounds anyway)
__device__ float g_zs[NN];
__device__ float g_zd[NN];
__device__ float g_vs[2][H], g_vd[2][H];  // Wg @ a_src, Wg @ a_dst (fp32, exact logits)
__device__ __half g_Wgh[2][H * H];        // fp16 Wg1, Wg2 (prepped once)
__device__ __half g_Wc1h[H * H];          // fp16 Wc1
__device__ int   g_cnt[NN];
__device__ int   g_col2[NN * SLOT];
__device__ float g_gamma1[NG * H], g_beta1[NG * H];
__device__ float g_gamma2[NG * H], g_beta2[NG * H];

__device__ __forceinline__ unsigned smem_u32(const void* p) {
    return (unsigned)__cvta_generic_to_shared(p);
}

#define LDSM_X4(r0, r1, r2, r3, addr)                                          \
    asm volatile("ldmatrix.sync.aligned.m8n8.x4.shared.b16 {%0,%1,%2,%3}, [%4];" \
                 : "=r"(r0), "=r"(r1), "=r"(r2), "=r"(r3) : "r"(addr))
#define LDSM_X4_T(r0, r1, r2, r3, addr)                                        \
    asm volatile("ldmatrix.sync.aligned.m8n8.x4.trans.shared.b16 {%0,%1,%2,%3}, [%4];" \
                 : "=r"(r0), "=r"(r1), "=r"(r2), "=r"(r3) : "r"(addr))
#define MMA16816(c, a0, a1, a2, a3, b0, b1)                                    \
    asm volatile("mma.sync.aligned.m16n8k16.row.col.f32.f16.f16.f32 "          \
                 "{%0,%1,%2,%3}, {%4,%5,%6,%7}, {%8,%9}, {%0,%1,%2,%3};"       \
                 : "+f"(c[0]), "+f"(c[1]), "+f"(c[2]), "+f"(c[3])              \
                 : "r"(a0), "r"(a1), "r"(a2), "r"(a3), "r"(b0), "r"(b1))

// ---------------- prep: climber MLP + FiLM + cnt zero + v vectors + fp16 weights --------
__global__ void k_climber_zero(const float* __restrict__ climber,
                               const float* __restrict__ ln_g, const float* __restrict__ ln_b,
                               const float* __restrict__ W_c,  const float* __restrict__ b_c,
                               const float* __restrict__ Wf1,  const float* __restrict__ bf1,
                               const float* __restrict__ Wf2,  const float* __restrict__ bf2,
                               const float* __restrict__ Wg1,  const float* __restrict__ as1,
                               const float* __restrict__ ad1,
                               const float* __restrict__ Wg2,  const float* __restrict__ as2,
                               const float* __restrict__ ad2,
                               const float* __restrict__ Wc1) {
    int t = threadIdx.x;
    if (blockIdx.x >= NG + NZB + 2) {
        // fp16 weight conversion: one block per matrix
        int which = blockIdx.x - (NG + NZB + 2);   // 0:Wg1 1:Wg2 2:Wc1
        const float* W = (which == 0) ? Wg1 : (which == 1) ? Wg2 : Wc1;
        __half* D = (which == 0) ? g_Wgh[0] : (which == 1) ? g_Wgh[1] : g_Wc1h;
        for (int i = t; i < H * H; i += 128) D[i] = __float2half(W[i]);
        return;
    }
    if (blockIdx.x >= NG + NZB) {
        // v = Wg @ a : which in {0:Wg1*as1, 1:Wg1*ad1, 2:Wg2*as2, 3:Wg2*ad2}
        int which = (blockIdx.x - (NG + NZB)) * 2 + (t >> 6);
        int k = t & 63;
        const float* W = (which < 2) ? Wg1 : Wg2;
        const float* a = (which & 1) ? ((which < 2) ? ad1 : ad2)
                                     : ((which < 2) ? as1 : as2);
        float v = 0.f;
#pragma unroll 8
        for (int j = 0; j < H; j++) v += W[k * H + j] * a[j];
        if (which & 1) g_vd[which >> 1][k] = v;
        else           g_vs[which >> 1][k] = v;
        return;
    }
    if (blockIdx.x >= NG) {
        int i = (blockIdx.x - NG) * 128 + t;
        if (i < NN) g_cnt[i] = 0;
        return;
    }
    __shared__ float cv[6], cn[6], c_sh[H];
    int g = blockIdx.x;
    if (t < 6) cv[t] = climber[g * 6 + t];
    __syncthreads();
    float mu = (cv[0] + cv[1] + cv[2] + cv[3] + cv[4] + cv[5]) * (1.0f / 6.0f);
    float var = 0.f;
#pragma unroll
    for (int k = 0; k < 6; k++) { float d = cv[k] - mu; var += d * d; }
    var *= (1.0f / 6.0f);
    float rstd = rsqrtf(var + 1e-5f);
    if (t < 6) cn[t] = (cv[t] - mu) * rstd * ln_g[t] + ln_b[t];
    __syncthreads();
    if (t < H) {
        float a = b_c[t];
#pragma unroll
        for (int k = 0; k < 6; k++) a += cn[k] * W_c[k * H + t];
        c_sh[t] = fmaxf(a, 0.f);
    }
    __syncthreads();
    float a1 = bf1[t], a2 = bf2[t];
    for (int k = 0; k < H; k++) {
        float cc = c_sh[k];
        a1 += cc * Wf1[k * 128 + t];
        a2 += cc * Wf2[k * 128 + t];
    }
    if (t < H) { g_gamma1[g * H + t] = a1; g_gamma2[g * H + t] = a2; }
    else       { g_beta1[g * H + t - H] = a1; g_beta2[g * H + t - H] = a2; }
}

// ---------------- padded-adjacency fill, 4 edges per thread (MLP=4) ----------------
__global__ void k_fill(const int* __restrict__ ei) {
    int t = blockIdx.x * blockDim.x + threadIdx.x;
    if (t < NE / 4) {
        int4 s4 = ((const int4*)ei)[t];
        int4 d4 = ((const int4*)(ei + NE))[t];
        int p;
        p = atomicAdd(&g_cnt[d4.x], 1); if (p < SLOT) g_col2[d4.x * SLOT + p] = s4.x;
        p = atomicAdd(&g_cnt[d4.y], 1); if (p < SLOT) g_col2[d4.y * SLOT + p] = s4.y;
        p = atomicAdd(&g_cnt[d4.z], 1); if (p < SLOT) g_col2[d4.z * SLOT + p] = s4.z;
        p = atomicAdd(&g_cnt[d4.w], 1); if (p < SLOT) g_col2[d4.w * SLOT + p] = s4.w;
    } else if (t < NE / 4 + NN / 4) {
        int n0 = (t - NE / 4) * 4;
#pragma unroll
        for (int k = 0; k < 4; k++) {
            int n = n0 + k;
            int p = atomicAdd(&g_cnt[n], 1);
            if (p < SLOT) g_col2[n * SLOT + p] = n;
        }
    }
}

// ---------------- FiLM (+ input proj) + tensor-core z GEMM + exact zs/zd ----------------
__global__ void k_film_z(int layer, const float* __restrict__ x,
                         const int* __restrict__ batch,
                         const float* __restrict__ Win, const float* __restrict__ bin) {
    __shared__ __half sW[H][72];
    __shared__ __half sA[32][72];
    __shared__ float  sC[32][68];
    __shared__ float  sWin[6][H];
    __shared__ float  sbin[H];
    __shared__ float  sx[32][8];
    __shared__ float  svs[H], svd[H];
    int t = threadIdx.x;
    int n0 = blockIdx.x * 32;
    // stage prepped fp16 weights via half2 copies (2048 half2 words)
    {
        const __half2* src = (const __half2*)g_Wgh[layer];
        for (int j = t; j < H * H / 2; j += 256)
            *(__half2*)&sW[j >> 5][(j & 31) * 2] = src[j];
    }
    if (t < H) { svs[t] = g_vs[layer][t]; svd[t] = g_vd[layer][t]; }
    if (layer == 0) {
        for (int i = t; i < 6 * H; i += 256) sWin[i >> 6][i & 63] = Win[i];
        if (t >= 64 && t < 128) sbin[t - 64] = bin[t - 64];
        sx[t >> 3][t & 7] = x[(n0 + (t >> 3)) * 8 + (t & 7)];
    }
    __syncthreads();

    // ---- stage 1: filmed hf (fp32), zs/zd (fp32), A tile (fp16) ----
    int nl = t >> 3, jb = (t & 7) * 8;
    int n = n0 + nl;
    int b = batch[n];
    const float* gam = ((layer == 0) ? g_gamma1 : g_gamma2) + b * H + jb;
    const float* bet = ((layer == 0) ? g_beta1  : g_beta2 ) + b * H + jb;
    float hf[8];
    if (layer == 0) {
        float xr[6];
#pragma unroll
        for (int k = 0; k < 6; k++) xr[k] = sx[nl][k];
#pragma unroll
        for (int j = 0; j < 8; j++) {
            float v = sbin[jb + j];
#pragma unroll
            for (int k = 0; k < 6; k++) v += xr[k] * sWin[k][jb + j];
            hf[j] = v;
        }
    } else {
        float4 h0 = *(const float4*)&g_hout[n * H + jb];
        float4 h1 = *(const float4*)&g_hout[n * H + jb + 4];
        hf[0] = h0.x; hf[1] = h0.y; hf[2] = h0.z; hf[3] = h0.w;
        hf[4] = h1.x; hf[5] = h1.y; hf[6] = h1.z; hf[7] = h1.w;
    }
    float4 ga = *(const float4*)&gam[0];
    float4 gb = *(const float4*)&gam[4];
    float4 ba = *(const float4*)&bet[0];
    float4 bb = *(const float4*)&bet[4];
    hf[0] = hf[0] * (1.f + ga.x) + ba.x;
    hf[1] = hf[1] * (1.f + ga.y) + ba.y;
    hf[2] = hf[2] * (1.f + ga.z) + ba.z;
    hf[3] = hf[3] * (1.f + ga.w) + ba.w;
    hf[4] = hf[4] * (1.f + gb.x) + bb.x;
    hf[5] = hf[5] * (1.f + gb.y) + bb.y;
    hf[6] = hf[6] * (1.f + gb.z) + bb.z;
    hf[7] = hf[7] * (1.f + gb.w) + bb.w;
    float ps = 0.f, pd = 0.f;
#pragma unroll
    for (int j = 0; j < 8; j++) { ps += hf[j] * svs[jb + j]; pd += hf[j] * svd[jb + j]; }
#pragma unroll
    for (int o = 4; o; o >>= 1) {
        ps += __shfl_xor_sync(0xffffffffu, ps, o);
        pd += __shfl_xor_sync(0xffffffffu, pd, o);
    }
    if ((t & 7) == 0) { g_zs[n] = ps; g_zd[n] = pd; }
    *(__half2*)&sA[nl][jb + 0] = __floats2half2_rn(hf[0], hf[1]);
    *(__half2*)&sA[nl][jb + 2] = __floats2half2_rn(hf[2], hf[3]);
    *(__half2*)&sA[nl][jb + 4] = __floats2half2_rn(hf[4], hf[5]);
    *(__half2*)&sA[nl][jb + 6] = __floats2half2_rn(hf[6], hf[7]);
    __syncthreads();

    // ---- GEMM: C[32x64] = A[32x64] x W[64x64], warp tiles M16 x N16 ----
    int w = t >> 5, l = t & 31;
    int mw = w >> 2, nw = w & 3;
    float c0[4] = {0.f, 0.f, 0.f, 0.f};
    float c1[4] = {0.f, 0.f, 0.f, 0.f};
    int arow = mw * 16 + (l & 15);
    int acol = (l >> 4) * 8;
    int brow = (l & 7) + ((l >> 3) & 1) * 8;
    int bcol = nw * 16 + (l >> 4) * 8;
#pragma unroll
    for (int kk = 0; kk < 4; kk++) {
        unsigned a0, a1, a2, a3, b0, b1, b2, b3;
        LDSM_X4(a0, a1, a2, a3, smem_u32(&sA[arow][kk * 16 + acol]));
        LDSM_X4_T(b0, b1, b2, b3, smem_u32(&sW[kk * 16 + brow][bcol]));
        MMA16816(c0, a0, a1, a2, a3, b0, b1);
        MMA16816(c1, a0, a1, a2, a3, b2, b3);
    }
    int row0 = mw * 16 + (l >> 2);
    int col0 = nw * 16 + (l & 3) * 2;
    sC[row0][col0]         = c0[0]; sC[row0][col0 + 1]     = c0[1];
    sC[row0 + 8][col0]     = c0[2]; sC[row0 + 8][col0 + 1] = c0[3];
    sC[row0][col0 + 8]     = c1[0]; sC[row0][col0 + 9]     = c1[1];
    sC[row0 + 8][col0 + 8] = c1[2]; sC[row0 + 8][col0 + 9] = c1[3];
    __syncthreads();

    // ---- epilogue: z -> fp16 global (coalesced) ----
    float4 z0 = *(float4*)&sC[nl][jb];
    float4 z1 = *(float4*)&sC[nl][jb + 4];
    __align__(16) __half ho[8];
    ho[0] = __float2half(z0.x); ho[1] = __float2half(z0.y);
    ho[2] = __float2half(z0.z); ho[3] = __float2half(z0.w);
    ho[4] = __float2half(z1.x); ho[5] = __float2half(z1.y);
    ho[6] = __float2half(z1.z); ho[7] = __float2half(z1.w);
    *(float4*)&g_zh[n * H + jb] = *(float4*)ho;
}

// ---------------- fused GAT: warp per 2 nodes; warp-coop softmax -> smem -> gather --------
// (wgt, off) packed in float2 smem -> single LDS.64 per edge in the gather loop.
__global__ void k_gat_ws(int layer, const float* __restrict__ bg) {
    __shared__ float2 swp[8][2][SLOT];   // .x = normalized weight, .y = offset bits
    int gw = (blockIdx.x * blockDim.x + threadIdx.x) >> 5;
    int wb = threadIdx.x >> 5;
    int lane = threadIdx.x & 31;
    int nl = lane >> 4, hl = lane & 15;
    int n = gw * 2 + nl;
    if (n >= NN) return;               // NN even: whole warp exits together
    int cnt = min(g_cnt[n], SLOT);
    int cmax = max(cnt, __shfl_xor_sync(0xffffffffu, cnt, 16));  // warp-uniform
    int rounds = (cmax + 15) >> 4;
    const int* __restrict__ cols = g_col2 + n * SLOT;
    float zdd = g_zd[n];
    float ev0 = -1e30f, ev1 = -1e30f, ev2 = -1e30f, ev3 = -1e30f;
#define LOGIT(r, ev)                                            \
    if (r < rounds) {                                           \
        int i = r * 16 + hl;                                    \
        int of = 0;                                             \
        if (i < cnt) {                                          \
            int s = cols[i];                                    \
            float tv = g_zs[s] + zdd;                           \
            ev = fmaxf(tv, 0.2f * tv);                          \
            of = s << 6;                                        \
        }                                                       \
        swp[wb][nl][i].y = __int_as_float(of);                  \
    }
    LOGIT(0, ev0) LOGIT(1, ev1) LOGIT(2, ev2) LOGIT(3, ev3)
#undef LOGIT
    float m = fmaxf(fmaxf(ev0, ev1), fmaxf(ev2, ev3));
#pragma unroll
    for (int o = 8; o; o >>= 1) m = fmaxf(m, __shfl_xor_sync(0xffffffffu, m, o));
    float w0 = __expf(ev0 - m), w1 = __expf(ev1 - m);
    float w2 = __expf(ev2 - m), w3 = __expf(ev3 - m);
    float sum = (w0 + w1) + (w2 + w3);
#pragma unroll
    for (int o = 8; o; o >>= 1) sum += __shfl_xor_sync(0xffffffffu, sum, o);
    float invs = 1.f / (sum + 1e-16f);
    if (0 < rounds) swp[wb][nl][hl].x      = w0 * invs;
    if (1 < rounds) swp[wb][nl][16 + hl].x = w1 * invs;
    if (2 < rounds) swp[wb][nl][32 + hl].x = w2 * invs;
    if (3 < rounds) swp[wb][nl][48 + hl].x = w3 * invs;
    __syncwarp();

    // phase 2: weighted gather (single LDS.64 per edge per lane)
    int g2 = (lane >> 3) & 1, ql = lane & 7;
    int trips = (cmax + 1) >> 1;
    const __half* __restrict__ zbase = g_zh + 8 * ql;
    float acc[8] = {0.f, 0.f, 0.f, 0.f, 0.f, 0.f, 0.f, 0.f};
#pragma unroll 4
    for (int j = 0; j < trips; j++) {
        int i = 2 * j + g2;
        float2 wo = swp[wb][nl][i];
        float wgt = wo.x;
        int   of  = __float_as_int(wo.y);
        float4 raw = *(const float4*)(zbase + of);
        const __half2* hp = (const __half2*)&raw;
        float2 f0 = __half22float2(hp[0]);
        float2 f1 = __half22float2(hp[1]);
        float2 f2 = __half22float2(hp[2]);
        float2 f3 = __half22float2(hp[3]);
        acc[0] += wgt * f0.x; acc[1] += wgt * f0.y;
        acc[2] += wgt * f1.x; acc[3] += wgt * f1.y;
        acc[4] += wgt * f2.x; acc[5] += wgt * f2.y;
        acc[6] += wgt * f3.x; acc[7] += wgt * f3.y;
    }
#pragma unroll
    for (int k = 0; k < 8; k++) acc[k] += __shfl_xor_sync(0xffffffffu, acc[k], 8);
    int fo = 8 * ql + 4 * g2;
    float4 bv = *(const float4*)&bg[fo];
    int ai = 4 * g2;
    float o0 = fmaxf(acc[ai + 0] + bv.x, 0.f);
    float o1 = fmaxf(acc[ai + 1] + bv.y, 0.f);
    float o2 = fmaxf(acc[ai + 2] + bv.z, 0.f);
    float o3 = fmaxf(acc[ai + 3] + bv.w, 0.f);
    if (layer == 0) {
        float4 oo = {o0, o1, o2, o3};
        *(float4*)&g_hout[n * H + fo] = oo;
    } else {
        // fp16 store — identical rounding to what k_cls applied previously
        __align__(8) __half2 ho[2];
        ho[0] = __floats2half2_rn(o0, o1);
        ho[1] = __floats2half2_rn(o2, o3);
        *(uint2*)&g_h2h[n * H + fo] = *(uint2*)ho;
    }
}

// ---------------- classifier (tensor-core) + flag head ----------------
__global__ void k_cls(const float* __restrict__ x,
                      const float* __restrict__ bc1,
                      const float* __restrict__ Wc2, const float* __restrict__ bc2,
                      const float* __restrict__ Wh1, const float* __restrict__ bh1,
                      const float* __restrict__ Wh2, const float* __restrict__ bh2,
                      float* __restrict__ out) {
    __shared__ __half sW[H][72];
    __shared__ __half sA[32][72];
    __shared__ float  sC[32][68];
    __shared__ float  sbc1[H];
    __shared__ float  sW2[H * 4];
    __shared__ float  sWh1[16], sbh1[8], sWh2[32], sbh2[4], sbc2[4];
    int t = threadIdx.x;
    int n0 = blockIdx.x * 32;
    {
        const __half2* src = (const __half2*)g_Wc1h;
        for (int j = t; j < H * H / 2; j += 256)
            *(__half2*)&sW[j >> 5][(j & 31) * 2] = src[j];
    }
    if (t < H) sbc1[t] = bc1[t];
    if (t < 256) sW2[t] = Wc2[t];
    if (t < 16) sWh1[t] = Wh1[t];
    if (t < 8)  sbh1[t] = bh1[t];
    if (t < 32) sWh2[t] = Wh2[t];
    if (t < 4)  { sbh2[t] = bh2[t]; sbc2[t] = bc2[t]; }
    // stage h2 rows (already fp16) — pure 16B copy
    int nl = t >> 3, jb = (t & 7) * 8;
    int n = n0 + nl;
    *(float4*)&sA[nl][jb] = *(const float4*)&g_h2h[n * H + jb];
    __syncthreads();

    // ---- GEMM: C[32x64] = A x Wc1 ----
    int w = t >> 5, l = t & 31;
    int mw = w >> 2, nw = w & 3;
    float c0[4] = {0.f, 0.f, 0.f, 0.f};
    float c1[4] = {0.f, 0.f, 0.f, 0.f};
    int arow = mw * 16 + (l & 15);
    int acol = (l >> 4) * 8;
    int brow = (l & 7) + ((l >> 3) & 1) * 8;
    int bcol = nw * 16 + (l >> 4) * 8;
#pragma unroll
    for (int kk = 0; kk < 4; kk++) {
        unsigned a0, a1, a2, a3, b0, b1, b2, b3;
        LDSM_X4(a0, a1, a2, a3, smem_u32(&sA[arow][kk * 16 + acol]));
        LDSM_X4_T(b0, b1, b2, b3, smem_u32(&sW[kk * 16 + brow][bcol]));
        MMA16816(c0, a0, a1, a2, a3, b0, b1);
        MMA16816(c1, a0, a1, a2, a3, b2, b3);
    }
    int row0 = mw * 16 + (l >> 2);
    int col0 = nw * 16 + (l & 3) * 2;
    sC[row0][col0]         = c0[0]; sC[row0][col0 + 1]     = c0[1];
    sC[row0 + 8][col0]     = c0[2]; sC[row0 + 8][col0 + 1] = c0[3];
    sC[row0][col0 + 8]     = c1[0]; sC[row0][col0 + 9]     = c1[1];
    sC[row0 + 8][col0 + 8] = c1[2]; sC[row0 + 8][col0 + 9] = c1[3];
    __syncthreads();

    // ---- final: relu(C+bc1) @ Wc2 + bc2 + 0.03*flag ----
    if (t < 128) {
        int onl = t >> 2, oj = t & 3;
        int on = n0 + onl;
        float cacc = sbc2[oj];
#pragma unroll
        for (int k = 0; k < H; k++)
            cacc += fmaxf(sC[onl][k] + sbc1[k], 0.f) * sW2[k * 4 + oj];
        float f0 = x[on * 8 + 6], f1 = x[on * 8 + 7];
        float facc = sbh2[oj];
#pragma unroll
        for (int m = 0; m < 8; m++) {
            float u = fmaxf(f0 * sWh1[m] + f1 * sWh1[8 + m] + sbh1[m], 0.f);
            facc += u * sWh2[m * 4 + oj];
        }
        out[on * 4 + oj] = cacc + 0.03f * facc;
    }
}

// ---------------- launch ----------------
extern "C" void kernel_launch(void* const* d_in, const int* in_sizes, int n_in,
                              void* d_out, int out_size) {
    const float* x       = (const float*)d_in[0];
    const int*   ei      = (const int*)  d_in[1];
    const int*   batch   = (const int*)  d_in[2];
    const float* climber = (const float*)d_in[3];
    const float* W_in    = (const float*)d_in[4];
    const float* b_in    = (const float*)d_in[5];
    const float* ln_g    = (const float*)d_in[6];
    const float* ln_b    = (const float*)d_in[7];
    const float* W_c     = (const float*)d_in[8];
    const float* b_c     = (const float*)d_in[9];
    const float* Wf1     = (const float*)d_in[10];
    const float* bf1     = (const float*)d_in[11];
    const float* Wf2     = (const float*)d_in[12];
    const float* bf2     = (const float*)d_in[13];
    const float* Wg1     = (const float*)d_in[14];
    const float* as1     = (const float*)d_in[15];
    const float* ad1     = (const float*)d_in[16];
    const float* bg1     = (const float*)d_in[17];
    const float* Wg2     = (const float*)d_in[18];
    const float* as2     = (const float*)d_in[19];
    const float* ad2     = (const float*)d_in[20];
    const float* bg2     = (const float*)d_in[21];
    const float* Wc1     = (const float*)d_in[22];
    const float* bc1     = (const float*)d_in[23];
    const float* Wc2     = (const float*)d_in[24];
    const float* bc2     = (const float*)d_in[25];
    const float* Wh1     = (const float*)d_in[26];
    const float* bh1     = (const float*)d_in[27];
    const float* Wh2     = (const float*)d_in[28];
    const float* bh2     = (const float*)d_in[29];
    float* out = (float*)d_out;

    k_climber_zero<<<NG + NZB + 5, 128>>>(climber, ln_g, ln_b, W_c, b_c,
                                          Wf1, bf1, Wf2, bf2,
                                          Wg1, as1, ad1, Wg2, as2, ad2, Wc1);
    k_fill<<<(NE / 4 + NN / 4 + 255) / 256, 256>>>(ei);

    k_film_z<<<NN / 32, 256>>>(0, x, batch, W_in, b_in);
    k_gat_ws<<<NN / 16, 256>>>(0, bg1);

    k_film_z<<<NN / 32, 256>>>(1, x, batch, W_in, b_in);
    k_gat_ws<<<NN / 16, 256>>>(1, bg2);

    k_cls<<<NN / 32, 256>>>(x, bc1, Wc2, bc2, Wh1, bh1, Wh2, bh2, out);
}